// round 10
// baseline (speedup 1.0000x reference)
#include <cuda_runtime.h>
#include <math.h>
#include <stdint.h>

typedef unsigned long long ull;

constexpr int B  = 2;
constexpr int C  = 32;
constexpr int NS = 32;
constexpr int NZ = 96;
constexpr int NX = 96;
constexpr int P  = NS * NZ * NX;
constexpr int NPT = B * P;
constexpr int M1 = 8, M2 = 12, M3 = 12;
constexpr int KS = 16, KZ = 24, KX = 12;
constexpr float SLOPE = 0.1f;
constexpr float INV2DX = 50.0f;

// ---------------- scratch ----------------
__device__ float  g_hA[B * C * P];
__device__ float  g_hB[B * C * P];
__device__ float2 g_S2[B * C * NS * KZ * KX];
__device__ float2 g_S3[B * C * KS * KZ * KX];
__device__ float2 g_G [B * C * KS * KZ * KX];
__device__ float  g_t0dx[NPT];
__device__ float  g_t0dz[NPT];
__device__ double g_sum[C];
__device__ double g_sq[C];
__device__ float  g_scaleL[4 * C];
__device__ float  g_shiftL[4 * C];

// packed twiddles
__device__ ulonglong2 g_twFxP[KX * 48];
__device__ ulonglong2 g_twFzP[KZ * NZ];
__device__ ulonglong2 g_twIzP[NZ * KZ];
__device__ ulonglong2 g_twIxP[48 * KX];
__device__ float2 g_twFs[KS * NS];
__device__ float2 g_twIs[NS * KS];

__device__ __forceinline__ float lrelu(float v) { return v > 0.f ? v : SLOPE * v; }
__device__ __forceinline__ float* hbuf(int s) { return s ? g_hB : g_hA; }
__device__ __forceinline__ ull pk(float a, float b) {
    ull r; asm("mov.b64 %0,{%1,%2};" : "=l"(r) : "f"(a), "f"(b)); return r;
}
__device__ __forceinline__ void upk(ull v, float& a, float& b) {
    asm("mov.b64 {%0,%1},%2;" : "=f"(a), "=f"(b) : "l"(v));
}
__device__ __forceinline__ ull fma2(ull a, ull b, ull c) {
    ull d; asm("fma.rn.f32x2 %0,%1,%2,%3;" : "=l"(d) : "l"(a), "l"(b), "l"(c)); return d;
}

// ---------------- twiddle init ----------------
__global__ void k_init_tw() {
    int t = blockIdx.x * blockDim.x + threadIdx.x;
    if (t < 576) {
        int k = t / 48, xh = t % 48;
        double s0, c0, s1, c1;
        sincospi(2.0 * double((k * (2 * xh)) % NX) / NX, &s0, &c0);
        sincospi(2.0 * double((k * (2 * xh + 1)) % NX) / NX, &s1, &c1);
        g_twFxP[t].x = pk((float)(c0 / NX), (float)(c1 / NX));
        g_twFxP[t].y = pk((float)(-s0 / NX), (float)(-s1 / NX));
    }
    if (t < 2304) {
        int kzi = t / 96, z = t % 96;
        int kz = (kzi < M2) ? kzi : kzi + (NZ - KZ);
        double s, c; sincospi(2.0 * double((kz * z) % NZ) / NZ, &s, &c);
        float tx = (float)(c / NZ), ty = (float)(-s / NZ);
        g_twFzP[t].x = pk(tx, ty); g_twFzP[t].y = pk(-ty, tx);
    }
    if (t < 2304) {
        int z = t / 24, k = t % 24;
        int kz = (k < M2) ? k : k + (NZ - KZ);
        double s, c; sincospi(2.0 * double((kz * z) % NZ) / NZ, &s, &c);
        float tx = (float)c, ty = (float)s;
        g_twIzP[t].x = pk(tx, ty); g_twIzP[t].y = pk(-ty, tx);
    }
    if (t < 576) {
        int xh = t / 12, k = t % 12;
        double s0, c0, s1, c1;
        sincospi(2.0 * double((k * (2 * xh)) % NX) / NX, &s0, &c0);
        sincospi(2.0 * double((k * (2 * xh + 1)) % NX) / NX, &s1, &c1);
        g_twIxP[t].x = pk((float)c0, (float)c1);
        g_twIxP[t].y = pk((float)(-s0), (float)(-s1));
    }
    if (t < 512) {
        int ksi = t / 32, s0i = t % 32;
        int ks = (ksi < M1) ? ksi : ksi + (NS - KS);
        double s, c; sincospi(2.0 * double((ks * s0i) % NS) / NS, &s, &c);
        g_twFs[t] = make_float2((float)(c / NS), (float)(-s / NS));
    }
    if (t < 512) {
        int s0i = t / 16, k = t % 16;
        int ks = (k < M1) ? k : k + (NS - KS);
        double s, c; sincospi(2.0 * double((ks * s0i) % NS) / NS, &s, &c);
        g_twIs[t] = make_float2((float)c, (float)s);
    }
}

// ---------------- fc0 + T0 derivatives ----------------
__global__ void k_fc0t0(const float* __restrict__ x, const float* __restrict__ w,
                        const float* __restrict__ bb) {
    int p = blockIdx.x * blockDim.x + threadIdx.x;
    if (p >= NPT) return;
    int b = p / P, p0 = p % P;
    int xx = p0 % NX;
    int z  = (p0 / NX) % NZ;
    float a0 = x[2 * p], a1 = x[2 * p + 1];
#pragma unroll
    for (int c = 0; c < C; c++)
        g_hA[(b * C + c) * P + p0] = a0 * w[c] + a1 * w[C + c] + bb[c];
    float xm = (xx > 0)      ? x[2 * (p - 1) + 1]  : 0.f;
    float xp = (xx < NX - 1) ? x[2 * (p + 1) + 1]  : 0.f;
    g_t0dx[p] = (xp - xm) * INV2DX;
    float zm = (z > 0)       ? x[2 * (p - NX) + 1] : 0.f;
    float zp = (z < NZ - 1)  ? x[2 * (p + NX) + 1] : 0.f;
    g_t0dz[p] = (zp - zm) * INV2DX;
}

// ---------------- fused forward DFT (x then z) per (b,c,s) slab ----------------
constexpr int SMEM_FWD = 64512;
__global__ void __launch_bounds__(256) k_fwd(int selIn, int Lprev) {
    extern __shared__ char smraw[];
    float* slab = (float*)smraw;
    ull*   s1re = (ull*)(smraw + 36864);
    ull*   s1im = (ull*)(smraw + 46080);
    ulonglong2* sFx = (ulonglong2*)(smraw + 55296);
    int bid = blockIdx.x, tid = threadIdx.x;
    int c = (bid / NS) % C;
    float sc = 1.f, sh = 0.f;
    if (Lprev >= 0) { sc = g_scaleL[Lprev * C + c]; sh = g_shiftL[Lprev * C + c]; }
    const float* base = hbuf(selIn) + (size_t)bid * 9216;
    for (int i = tid; i < 9216; i += 256) {
        float v = base[i];
        if (Lprev >= 0) v = lrelu(fmaf(v, sc, sh));
        slab[i] = v;
    }
    for (int i = tid; i < 576; i += 256) sFx[i] = g_twFxP[i];
    __syncthreads();
    for (int it = tid; it < 1152; it += 256) {
        int k = it % 12, z = it / 12;
        ull ar0 = 0, ar1 = 0, ai0 = 0, ai1 = 0;
        const float* row = slab + z * 96;
        const ulonglong2* tw = sFx + k * 48;
#pragma unroll 6
        for (int xh = 0; xh < 48; xh += 2) {
            ull v0 = *(const ull*)(row + 2 * xh);
            ull v1 = *(const ull*)(row + 2 * xh + 2);
            ulonglong2 t0 = tw[xh], t1 = tw[xh + 1];
            ar0 = fma2(v0, t0.x, ar0);
            ai0 = fma2(v0, t0.y, ai0);
            ar1 = fma2(v1, t1.x, ar1);
            ai1 = fma2(v1, t1.y, ai1);
        }
        float r0, r1, r2, r3, i0, i1, i2, i3;
        upk(ar0, r0, r1); upk(ar1, r2, r3); upk(ai0, i0, i1); upk(ai1, i2, i3);
        float re = (r0 + r1) + (r2 + r3), im = (i0 + i1) + (i2 + i3);
        s1re[it] = pk(re, re);
        s1im[it] = pk(im, im);
    }
    __syncthreads();
    for (int it = tid; it < 288; it += 256) {
        int kx = it % 12, kz = it / 12;
        ull a0 = 0, a1 = 0;
        const ulonglong2* tw = g_twFzP + kz * 96;
#pragma unroll 4
        for (int z = 0; z < 96; z += 2) {
            ulonglong2 t0 = tw[z], t1 = tw[z + 1];
            a0 = fma2(s1re[z * 12 + kx], t0.x, a0);
            a0 = fma2(s1im[z * 12 + kx], t0.y, a0);
            a1 = fma2(s1re[(z + 1) * 12 + kx], t1.x, a1);
            a1 = fma2(s1im[(z + 1) * 12 + kx], t1.y, a1);
        }
        float u0, u1, v0, v1; upk(a0, u0, u1); upk(a1, v0, v1);
        g_S2[(size_t)bid * 288 + it] = make_float2(u0 + v0, u1 + v1);
    }
}

// ---------------- forward s-DFT ----------------
__global__ void k_f3() {
    int g = blockIdx.x * blockDim.x + threadIdx.x;
    int kx = g % KX, kzi = (g / KX) % KZ, ksi = (g / 288) % KS, bc = g / 4608;
    const float2* src = g_S2 + bc * NS * 288 + kzi * KX + kx;
    const float2* tw  = g_twFs + ksi * NS;
    float re0 = 0.f, im0 = 0.f, re1 = 0.f, im1 = 0.f;
#pragma unroll 4
    for (int s = 0; s < NS; s += 2) {
        float2 v0 = src[s * 288], t0 = tw[s];
        float2 v1 = src[(s + 1) * 288], t1 = tw[s + 1];
        re0 += v0.x * t0.x - v0.y * t0.y;
        im0 += v0.x * t0.y + v0.y * t0.x;
        re1 += v1.x * t1.x - v1.y * t1.y;
        im1 += v1.x * t1.y + v1.y * t1.x;
    }
    g_S3[(bc * KS + ksi) * 288 + kzi * KX + kx] = make_float2(re0 + re1, im0 + im1);
}

// ---------------- spectral multiply ----------------
__global__ void k_mul(int L, const float* __restrict__ spec) {
    int g = blockIdx.x * blockDim.x + threadIdx.x;
    int kx = g % KX, kzi = (g / KX) % KZ, ksi = (g / 288) % KS;
    int co = (g / 4608) % C, b = g / (4608 * C);
    int corner = (ksi >= M1 ? 1 : 0) + (kzi >= M2 ? 2 : 0);
    int k1 = (ksi >= M1) ? ksi - M1 : ksi;
    int k2 = (kzi >= M2) ? kzi - M2 : kzi;
    int wbase = ((((L * 4 + corner) * C) * C + co) * M1 + k1) * M2 + k2;
    wbase = wbase * M3 + kx;
    const int wstride = C * M1 * M2 * M3;
    const float2* xin = g_S3 + (b * C) * 4608 + ksi * 288 + kzi * KX + kx;
    const float2* wp  = (const float2*)spec + wbase;
    float re0 = 0.f, im0 = 0.f, re1 = 0.f, im1 = 0.f;
#pragma unroll 4
    for (int ci = 0; ci < C; ci += 2) {
        float2 a0 = xin[ci * 4608], w0 = wp[ci * wstride];
        float2 a1 = xin[(ci + 1) * 4608], w1 = wp[(ci + 1) * wstride];
        re0 += a0.x * w0.x - a0.y * w0.y;
        im0 += a0.x * w0.y + a0.y * w0.x;
        re1 += a1.x * w1.x - a1.y * w1.y;
        im1 += a1.x * w1.y + a1.y * w1.x;
    }
    g_G[g] = make_float2(re0 + re1, im0 + im1);
}

// ---------------- fused inverse DFT (s, z, x) per (b,c,s) slab ----------------
constexpr int SMEM_INV = 69120;
__global__ void __launch_bounds__(256) k_inv(int selOut) {
    extern __shared__ char smraw[];
    float2* sG  = (float2*)smraw;
    ull* T1re = (ull*)(smraw + 36864);
    ull* T1im = (ull*)(smraw + 39168);
    ull* T2re = (ull*)(smraw + 41472);
    ull* T2im = (ull*)(smraw + 50688);
    ulonglong2* sIx = (ulonglong2*)(smraw + 59904);
    __shared__ float2 sTs[16];
    int bid = blockIdx.x, tid = threadIdx.x;
    int s = bid % NS, bc = bid / NS;
    for (int i = tid; i < 4608; i += 256) sG[i] = g_G[(size_t)bc * 4608 + i];
    for (int i = tid; i < 576;  i += 256) sIx[i] = g_twIxP[i];
    if (tid < 16) sTs[tid] = g_twIs[s * 16 + tid];
    __syncthreads();
    for (int it = tid; it < 288; it += 256) {
        float re0 = 0.f, im0 = 0.f, re1 = 0.f, im1 = 0.f;
#pragma unroll
        for (int k = 0; k < 16; k += 2) {
            float2 v0 = sG[k * 288 + it], t0 = sTs[k];
            float2 v1 = sG[(k + 1) * 288 + it], t1 = sTs[k + 1];
            re0 += v0.x * t0.x - v0.y * t0.y;
            im0 += v0.x * t0.y + v0.y * t0.x;
            re1 += v1.x * t1.x - v1.y * t1.y;
            im1 += v1.x * t1.y + v1.y * t1.x;
        }
        float re = re0 + re1, im = im0 + im1;
        T1re[it] = pk(re, re); T1im[it] = pk(im, im);
    }
    __syncthreads();
    for (int it = tid; it < 1152; it += 256) {
        int kx = it % 12, z = it / 12;
        ull a0 = 0, a1 = 0;
        const ulonglong2* tw = g_twIzP + z * 24;
#pragma unroll
        for (int k = 0; k < 24; k += 2) {
            ulonglong2 t0 = tw[k], t1 = tw[k + 1];
            a0 = fma2(T1re[k * 12 + kx], t0.x, a0);
            a0 = fma2(T1im[k * 12 + kx], t0.y, a0);
            a1 = fma2(T1re[(k + 1) * 12 + kx], t1.x, a1);
            a1 = fma2(T1im[(k + 1) * 12 + kx], t1.y, a1);
        }
        float u0, u1, v0, v1; upk(a0, u0, u1); upk(a1, v0, v1);
        float re = u0 + v0, im = u1 + v1;
        T2re[it] = pk(re, re); T2im[it] = pk(im, im);
    }
    __syncthreads();
    float* dst = hbuf(selOut) + (size_t)bid * 9216;
    for (int it = tid; it < 4608; it += 256) {
        int xh = it % 48, z = it / 48;
        ull a0 = 0, a1 = 0;
        const ulonglong2* tw = sIx + xh * 12;
#pragma unroll
        for (int k = 0; k < 12; k += 2) {
            ulonglong2 t0 = tw[k], t1 = tw[k + 1];
            a0 = fma2(T2re[z * 12 + k], t0.x, a0);
            a0 = fma2(T2im[z * 12 + k], t0.y, a0);
            a1 = fma2(T2re[z * 12 + k + 1], t1.x, a1);
            a1 = fma2(T2im[z * 12 + k + 1], t1.y, a1);
        }
        float u0, u1, v0, v1; upk(a0, u0, u1); upk(a1, v0, v1);
        *(float2*)(dst + z * 96 + 2 * xh) = make_float2(u0 + v0, u1 + v1);
    }
}

// ---------------- pointwise conv: OUT += W*act(BN(IN)) + b ----------------
__global__ void __launch_bounds__(256) k_w2(int selIn, int selOut, int Lprev, int L,
                                            const float* __restrict__ ww,
                                            const float* __restrict__ wb) {
    __shared__ ull sWP[C * 16];
    __shared__ float sB[32], sSc[32], sSh[32];
    int tid = threadIdx.x;
    for (int i = tid; i < 512; i += 256) {
        int cop = i & 15, ci = i >> 4;
        sWP[i] = pk(ww[L * 1024 + (2 * cop) * C + ci],
                    ww[L * 1024 + (2 * cop + 1) * C + ci]);
    }
    if (tid < 32) {
        sB[tid] = wb[L * C + tid];
        if (Lprev >= 0) { sSc[tid] = g_scaleL[Lprev * C + tid]; sSh[tid] = g_shiftL[Lprev * C + tid]; }
        else            { sSc[tid] = 1.f; sSh[tid] = 0.f; }
    }
    __syncthreads();
    int p = blockIdx.x * 256 + tid;
    int b = p / P, p0 = p % P;
    const float* h = hbuf(selIn) + b * C * P + p0;
    ull acc[16];
#pragma unroll
    for (int cop = 0; cop < 16; cop++) acc[cop] = pk(sB[2 * cop], sB[2 * cop + 1]);
    int useBn = (Lprev >= 0);
#pragma unroll
    for (int ci = 0; ci < 32; ci++) {
        float v = h[ci * P];
        if (useBn) v = lrelu(fmaf(v, sSc[ci], sSh[ci]));
        ull vp = pk(v, v);
        const ulonglong2* wr = (const ulonglong2*)&sWP[ci * 16];
#pragma unroll
        for (int q = 0; q < 8; q++) {
            ulonglong2 w = wr[q];
            acc[2 * q]     = fma2(vp, w.x, acc[2 * q]);
            acc[2 * q + 1] = fma2(vp, w.y, acc[2 * q + 1]);
        }
    }
    float* o = hbuf(selOut) + b * C * P + p0;
#pragma unroll
    for (int cop = 0; cop < 16; cop++) {
        float f0, f1; upk(acc[cop], f0, f1);
        o[(2 * cop) * P]     += f0;
        o[(2 * cop + 1) * P] += f1;
    }
}

// ---------------- batchnorm stats ----------------
__global__ void k_zero() {
    if (threadIdx.x < C) { g_sum[threadIdx.x] = 0.0; g_sq[threadIdx.x] = 0.0; }
}

__global__ void __launch_bounds__(256) k_stat(int selOut) {
    int bid = blockIdx.x;                       // B*C*(P/4096) = 4608 blocks
    int c = (bid / (P / 4096)) % C;
    const float4* src = (const float4*)(hbuf(selOut) + (size_t)bid * 4096);
    float s = 0.f, q = 0.f;
#pragma unroll
    for (int r = 0; r < 4; r++) {
        float4 v = src[threadIdx.x + 256 * r];
        s += (v.x + v.y) + (v.z + v.w);
        q += (v.x * v.x + v.y * v.y) + (v.z * v.z + v.w * v.w);
    }
#pragma unroll
    for (int o = 16; o; o >>= 1) {
        s += __shfl_down_sync(0xffffffffu, s, o);
        q += __shfl_down_sync(0xffffffffu, q, o);
    }
    __shared__ float ws[8], wq[8];
    int wid = threadIdx.x >> 5, lane = threadIdx.x & 31;
    if (lane == 0) { ws[wid] = s; wq[wid] = q; }
    __syncthreads();
    if (threadIdx.x == 0) {
        float S = 0.f, Q = 0.f;
        for (int i = 0; i < 8; i++) { S += ws[i]; Q += wq[i]; }
        atomicAdd(&g_sum[c], (double)S);
        atomicAdd(&g_sq[c],  (double)Q);
    }
}

__global__ void k_fin(int L, const float* __restrict__ bg, const float* __restrict__ bb) {
    int c = threadIdx.x;
    if (c < C) {
        double n = (double)NPT;
        double m = g_sum[c] / n;
        double var = g_sq[c] / n - m * m;
        float sc = bg[L * C + c] * (float)(1.0 / sqrt(var + 1e-5));
        g_scaleL[L * C + c] = sc;
        g_shiftL[L * C + c] = bb[L * C + c] - (float)m * sc;
        g_sum[c] = 0.0;                  // reset for next layer
        g_sq[c]  = 0.0;
    }
}

// ---------------- fused MLP + mask (f32x2, transposed weights, occ 2) ----------------
constexpr int OW1T = 0,      OB1 = 4096;
constexpr int OW2  = 4224,   OB2 = 12416;
constexpr int OW3T = 12480,  OB3 = 14528;
constexpr int OW4T = 14560,  OB4 = 16608;
constexpr int OW5T = 16672,  OB5 = 24864;
constexpr int OW7  = 24992,  OB7 = 25120;
constexpr int OSC  = 25121,  OSH = 25153;
constexpr int SMEM_MLP = 25185 * 4;

__global__ void __launch_bounds__(256, 2) k_mlp(
    const float* __restrict__ x,
    const float* __restrict__ w1, const float* __restrict__ b1,
    const float* __restrict__ w2, const float* __restrict__ b2,
    const float* __restrict__ w3, const float* __restrict__ b3,
    const float* __restrict__ w4, const float* __restrict__ b4,
    const float* __restrict__ w5, const float* __restrict__ b5,
    const float* __restrict__ w7, const float* __restrict__ b7,
    float* __restrict__ out) {
    extern __shared__ float sm[];
    int tid = threadIdx.x;
    for (int i = tid; i < 4096; i += 256) {          // w1 transpose [j][i]
        int r = i >> 7, j = i & 127;
        sm[OW1T + j * 32 + r] = w1[i];
    }
    for (int i = tid; i < 128;  i += 256) sm[OB1 + i] = b1[i];
    for (int i = tid; i < 8192; i += 256) sm[OW2 + i] = w2[i];   // row-major [j][k]
    for (int i = tid; i < 64;   i += 256) sm[OB2 + i] = b2[i];
    for (int i = tid; i < 2048; i += 256) {          // w3 transpose [k][j]
        int j = i >> 5, k = i & 31;
        sm[OW3T + k * 64 + j] = w3[i];
    }
    for (int i = tid; i < 32;   i += 256) sm[OB3 + i] = b3[i];
    for (int i = tid; i < 2048; i += 256) {          // w4 transpose [k][j]
        int j = i >> 6, k = i & 63;
        sm[OW4T + k * 32 + j] = w4[i];
    }
    for (int i = tid; i < 64;   i += 256) sm[OB4 + i] = b4[i];
    for (int i = tid; i < 8192; i += 256) {          // w5 transpose [k][j]
        int j = i >> 7, k = i & 127;
        sm[OW5T + k * 64 + j] = w5[i];
    }
    for (int i = tid; i < 128;  i += 256) sm[OB5 + i] = b5[i];
    for (int i = tid; i < 128;  i += 256) sm[OW7 + i] = w7[i];
    if (tid == 0) sm[OB7] = b7[0];
    if (tid < 32) { sm[OSC + tid] = g_scaleL[3 * C + tid]; sm[OSH + tid] = g_shiftL[3 * C + tid]; }
    __syncthreads();

    int p = blockIdx.x * 256 + tid;
    int b = p / P, p0 = p % P;
    const float* h = g_hA + b * C * P + p0;
    ull inl[16];
#pragma unroll
    for (int i = 0; i < 16; i++) {
        float v0 = lrelu(fmaf(h[(2 * i) * P],     sm[OSC + 2 * i],     sm[OSH + 2 * i]));
        float v1 = lrelu(fmaf(h[(2 * i + 1) * P], sm[OSC + 2 * i + 1], sm[OSH + 2 * i + 1]));
        inl[i] = pk(v0, v1);
    }

    // fc1 (reduce over i, one j/iter) interleaved with fc2 accumulation
    ull a2[32];
#pragma unroll
    for (int k = 0; k < 32; k++) a2[k] = *(const ull*)&sm[OB2 + 2 * k];
#pragma unroll 1
    for (int j = 0; j < 128; j++) {
        ull c0 = 0, c1 = 0;
        const ulonglong2* wr = (const ulonglong2*)&sm[OW1T + j * 32];
#pragma unroll
        for (int m = 0; m < 8; m++) {
            ulonglong2 t = wr[m];
            c0 = fma2(inl[2 * m], t.x, c0);
            c1 = fma2(inl[2 * m + 1], t.y, c1);
        }
        float u0, u1, u2, u3;
        upk(c0, u0, u1); upk(c1, u2, u3);
        float a = lrelu((u0 + u1) + (u2 + u3) + sm[OB1 + j]);
        ull q = pk(a, a);
        const ulonglong2* r = (const ulonglong2*)&sm[OW2 + j * 64];
#pragma unroll
        for (int m = 0; m < 16; m++) {
            ulonglong2 t = r[m];
            a2[2 * m]     = fma2(q, t.x, a2[2 * m]);
            a2[2 * m + 1] = fma2(q, t.y, a2[2 * m + 1]);
        }
    }
#pragma unroll
    for (int k = 0; k < 32; k++) {
        float u, v; upk(a2[k], u, v);
        a2[k] = pk(lrelu(u), lrelu(v));
    }

    // fc3: 64 -> 32 (reduce, transposed w3), one output pair per iter
    ull a3l[16];
#pragma unroll 1
    for (int k = 0; k < 32; k += 2) {
        ull c0 = 0, c1 = 0, d0 = 0, d1 = 0;
        const ulonglong2* r0 = (const ulonglong2*)&sm[OW3T + k * 64];
        const ulonglong2* r1 = (const ulonglong2*)&sm[OW3T + (k + 1) * 64];
#pragma unroll
        for (int m = 0; m < 16; m++) {
            ulonglong2 t0 = r0[m], t1 = r1[m];
            c0 = fma2(a2[2 * m], t0.x, c0);
            c1 = fma2(a2[2 * m + 1], t0.y, c1);
            d0 = fma2(a2[2 * m], t1.x, d0);
            d1 = fma2(a2[2 * m + 1], t1.y, d1);
        }
        float u0, u1, u2, u3, v0, v1, v2, v3;
        upk(c0, u0, u1); upk(c1, u2, u3); upk(d0, v0, v1); upk(d1, v2, v3);
        a3l[k >> 1] = pk(lrelu((u0 + u1) + (u2 + u3) + sm[OB3 + k]),
                         lrelu((v0 + v1) + (v2 + v3) + sm[OB3 + k + 1]));
    }

    // fc4: 32 -> 64
    ull a4l[32];
#pragma unroll 1
    for (int k = 0; k < 64; k += 2) {
        ull c0 = 0, c1 = 0, d0 = 0, d1 = 0;
        const ulonglong2* r0 = (const ulonglong2*)&sm[OW4T + k * 32];
        const ulonglong2* r1 = (const ulonglong2*)&sm[OW4T + (k + 1) * 32];
#pragma unroll
        for (int m = 0; m < 8; m++) {
            ulonglong2 t0 = r0[m], t1 = r1[m];
            c0 = fma2(a3l[2 * m], t0.x, c0);
            c1 = fma2(a3l[2 * m + 1], t0.y, c1);
            d0 = fma2(a3l[2 * m], t1.x, d0);
            d1 = fma2(a3l[2 * m + 1], t1.y, d1);
        }
        float u0, u1, u2, u3, v0, v1, v2, v3;
        upk(c0, u0, u1); upk(c1, u2, u3); upk(d0, v0, v1); upk(d1, v2, v3);
        a4l[k >> 1] = pk(lrelu((u0 + u1) + (u2 + u3) + sm[OB4 + k]),
                         lrelu((v0 + v1) + (v2 + v3) + sm[OB4 + k + 1]));
    }

    // fc5: 64 -> 128 streamed into fc7
    float tau = sm[OB7];
#pragma unroll 1
    for (int k = 0; k < 128; k += 2) {
        ull c0 = 0, c1 = 0, d0 = 0, d1 = 0;
        const ulonglong2* r0 = (const ulonglong2*)&sm[OW5T + k * 64];
        const ulonglong2* r1 = (const ulonglong2*)&sm[OW5T + (k + 1) * 64];
#pragma unroll
        for (int m = 0; m < 16; m++) {
            ulonglong2 t0 = r0[m], t1 = r1[m];
            c0 = fma2(a4l[2 * m], t0.x, c0);
            c1 = fma2(a4l[2 * m + 1], t0.y, c1);
            d0 = fma2(a4l[2 * m], t1.x, d0);
            d1 = fma2(a4l[2 * m + 1], t1.y, d1);
        }
        float u0, u1, u2, u3, v0, v1, v2, v3;
        upk(c0, u0, u1); upk(c1, u2, u3); upk(d0, v0, v1); upk(d1, v2, v3);
        float a5a = lrelu((u0 + u1) + (u2 + u3) + sm[OB5 + k]);
        float a5b = lrelu((v0 + v1) + (v2 + v3) + sm[OB5 + k + 1]);
        tau += a5a * sm[OW7 + k] + a5b * sm[OW7 + k + 1];
    }

    float T0 = x[2 * p + 1];
    int z = (p0 / NX) % NZ;
    float mask = (z < 2) ? 0.f : ((T0 < 0.01f) ? T0 : 1.f);
    out[p] = tau * mask;
}

// ---------------- loss ----------------
__global__ void k_loss(const float* __restrict__ y, float* __restrict__ out) {
    int p = blockIdx.x * blockDim.x + threadIdx.x;
    if (p >= NPT) return;
    int p0 = p % P;
    int xx = p0 % NX;
    int z = (p0 / NX) % NZ;
    const float* tau = out;
    float tm = (xx > 0)      ? tau[p - 1]  : 0.f;
    float tp = (xx < NX - 1) ? tau[p + 1]  : 0.f;
    float dx = (tp - tm) * INV2DX + g_t0dx[p];
    float zm = (z > 0)       ? tau[p - NX] : 0.f;
    float zp = (z < NZ - 1)  ? tau[p + NX] : 0.f;
    float dz = (zp - zm) * INV2DX + g_t0dz[p];
    out[NPT + p] = dx * dx + dz * dz - y[p];
}

// ---------------- launch ----------------
extern "C" void kernel_launch(void* const* d_in, const int* in_sizes, int n_in,
                              void* d_out, int out_size) {
    const float* x      = (const float*)d_in[0];
    const float* y      = (const float*)d_in[1];
    const float* fc0_w  = (const float*)d_in[2];
    const float* fc0_b  = (const float*)d_in[3];
    const float* spec_w = (const float*)d_in[4];
    const float* w_w    = (const float*)d_in[5];
    const float* w_b    = (const float*)d_in[6];
    const float* bn_g   = (const float*)d_in[7];
    const float* bn_b   = (const float*)d_in[8];
    const float* fc1_w  = (const float*)d_in[9];
    const float* fc1_b  = (const float*)d_in[10];
    const float* fc2_w  = (const float*)d_in[11];
    const float* fc2_b  = (const float*)d_in[12];
    const float* fc3_w  = (const float*)d_in[13];
    const float* fc3_b  = (const float*)d_in[14];
    const float* fc4_w  = (const float*)d_in[15];
    const float* fc4_b  = (const float*)d_in[16];
    const float* fc5_w  = (const float*)d_in[17];
    const float* fc5_b  = (const float*)d_in[18];
    const float* fc7_w  = (const float*)d_in[19];
    const float* fc7_b  = (const float*)d_in[20];
    float* out = (float*)d_out;

    cudaFuncSetAttribute(k_fwd, cudaFuncAttributeMaxDynamicSharedMemorySize, SMEM_FWD);
    cudaFuncSetAttribute(k_inv, cudaFuncAttributeMaxDynamicSharedMemorySize, SMEM_INV);
    cudaFuncSetAttribute(k_mlp, cudaFuncAttributeMaxDynamicSharedMemorySize, SMEM_MLP);

    k_init_tw<<<9, 256>>>();
    k_zero<<<1, 32>>>();
    k_fc0t0<<<NPT / 256, 256>>>(x, fc0_w, fc0_b);

    for (int L = 0; L < 4; L++) {
        int in = L & 1, outb = 1 - in, Lp = L - 1;
        k_fwd<<<B * C * NS, 256, SMEM_FWD>>>(in, Lp);
        k_f3<<<(B * C * KS * KZ * KX) / 256, 256>>>();
        k_mul<<<(B * C * KS * KZ * KX) / 256, 256>>>(L, spec_w);
        k_inv<<<B * C * NS, 256, SMEM_INV>>>(outb);
        k_w2<<<NPT / 256, 256>>>(in, outb, Lp, L, w_w, w_b);
        k_stat<<<B * C * (P / 4096), 256>>>(outb);
        k_fin<<<1, 32>>>(L, bn_g, bn_b);
    }

    k_mlp<<<NPT / 256, 256, SMEM_MLP>>>(x,
        fc1_w, fc1_b, fc2_w, fc2_b, fc3_w, fc3_b,
        fc4_w, fc4_b, fc5_w, fc5_b, fc7_w, fc7_b, out);
    k_loss<<<NPT / 256, 256>>>(y, out);
}

// round 13
// speedup vs baseline: 1.7046x; 1.7046x over previous
#include <cuda_runtime.h>
#include <math.h>
#include <stdint.h>

typedef unsigned long long ull;

constexpr int B  = 2;
constexpr int C  = 32;
constexpr int NS = 32;
constexpr int NZ = 96;
constexpr int NX = 96;
constexpr int P  = NS * NZ * NX;
constexpr int NPT = B * P;
constexpr int M1 = 8, M2 = 12, M3 = 12;
constexpr int KS = 16, KZ = 24, KX = 12;
constexpr float SLOPE = 0.1f;
constexpr float INV2DX = 50.0f;

// ---------------- scratch ----------------
__device__ float  g_hA[B * C * P];
__device__ float  g_hB[B * C * P];
__device__ float2 g_S2[B * C * NS * KZ * KX];
__device__ float2 g_S3[B * C * KS * KZ * KX];
__device__ float2 g_G [B * C * KS * KZ * KX];
__device__ float  g_t0dx[NPT];
__device__ float  g_t0dz[NPT];
__device__ double g_sum[C];
__device__ double g_sq[C];
__device__ float  g_scaleL[4 * C];
__device__ float  g_shiftL[4 * C];

// packed twiddles (TRANSPOSED so the lane-varying index is contiguous)
__device__ ulonglong2 g_twFxT[48 * KX];   // [xh][k]  : ((c0,c1),(-s0,-s1))/NX
__device__ ulonglong2 g_twFzP[KZ * NZ];   // [kz][z]  : ((c,s'),(-s',c))/NZ  (global reads, L1)
__device__ ulonglong2 g_twIzP[NZ * KZ];   // [z][k]
__device__ ulonglong2 g_twIxT[KX * 48];   // [k][xh]  : ((c0,c1),(-s0,-s1))
__device__ float2 g_twFs[KS * NS];
__device__ float2 g_twIs[NS * KS];

__device__ __forceinline__ float lrelu(float v) { return v > 0.f ? v : SLOPE * v; }
__device__ __forceinline__ float* hbuf(int s) { return s ? g_hB : g_hA; }
__device__ __forceinline__ ull pk(float a, float b) {
    ull r; asm("mov.b64 %0,{%1,%2};" : "=l"(r) : "f"(a), "f"(b)); return r;
}
__device__ __forceinline__ void upk(ull v, float& a, float& b) {
    asm("mov.b64 {%0,%1},%2;" : "=f"(a), "=f"(b) : "l"(v));
}
__device__ __forceinline__ ull fma2(ull a, ull b, ull c) {
    ull d; asm("fma.rn.f32x2 %0,%1,%2,%3;" : "=l"(d) : "l"(a), "l"(b), "l"(c)); return d;
}

// ---------------- twiddle init ----------------
__global__ void k_init_tw() {
    int t = blockIdx.x * blockDim.x + threadIdx.x;
    if (t < 576) {                       // FxT: [xh][k], xh = t/12, k = t%12
        int xh = t / 12, k = t % 12;
        double s0, c0, s1, c1;
        sincospi(2.0 * double((k * (2 * xh)) % NX) / NX, &s0, &c0);
        sincospi(2.0 * double((k * (2 * xh + 1)) % NX) / NX, &s1, &c1);
        g_twFxT[t].x = pk((float)(c0 / NX), (float)(c1 / NX));
        g_twFxT[t].y = pk((float)(-s0 / NX), (float)(-s1 / NX));
    }
    if (t < 2304) {
        int kzi = t / 96, z = t % 96;
        int kz = (kzi < M2) ? kzi : kzi + (NZ - KZ);
        double s, c; sincospi(2.0 * double((kz * z) % NZ) / NZ, &s, &c);
        float tx = (float)(c / NZ), ty = (float)(-s / NZ);
        g_twFzP[t].x = pk(tx, ty); g_twFzP[t].y = pk(-ty, tx);
    }
    if (t < 2304) {
        int z = t / 24, k = t % 24;
        int kz = (k < M2) ? k : k + (NZ - KZ);
        double s, c; sincospi(2.0 * double((kz * z) % NZ) / NZ, &s, &c);
        float tx = (float)c, ty = (float)s;
        g_twIzP[t].x = pk(tx, ty); g_twIzP[t].y = pk(-ty, tx);
    }
    if (t < 576) {                       // IxT: [k][xh], k = t/48, xh = t%48
        int k = t / 48, xh = t % 48;
        double s0, c0, s1, c1;
        sincospi(2.0 * double((k * (2 * xh)) % NX) / NX, &s0, &c0);
        sincospi(2.0 * double((k * (2 * xh + 1)) % NX) / NX, &s1, &c1);
        g_twIxT[t].x = pk((float)c0, (float)c1);
        g_twIxT[t].y = pk((float)(-s0), (float)(-s1));
    }
    if (t < 512) {
        int ksi = t / 32, s0i = t % 32;
        int ks = (ksi < M1) ? ksi : ksi + (NS - KS);
        double s, c; sincospi(2.0 * double((ks * s0i) % NS) / NS, &s, &c);
        g_twFs[t] = make_float2((float)(c / NS), (float)(-s / NS));
    }
    if (t < 512) {
        int s0i = t / 16, k = t % 16;
        int ks = (k < M1) ? k : k + (NS - KS);
        double s, c; sincospi(2.0 * double((ks * s0i) % NS) / NS, &s, &c);
        g_twIs[t] = make_float2((float)c, (float)s);
    }
}

// ---------------- fc0 + T0 derivatives ----------------
__global__ void k_fc0t0(const float* __restrict__ x, const float* __restrict__ w,
                        const float* __restrict__ bb) {
    int p = blockIdx.x * blockDim.x + threadIdx.x;
    if (p >= NPT) return;
    int b = p / P, p0 = p % P;
    int xx = p0 % NX;
    int z  = (p0 / NX) % NZ;
    float a0 = x[2 * p], a1 = x[2 * p + 1];
#pragma unroll
    for (int c = 0; c < C; c++)
        g_hA[(b * C + c) * P + p0] = a0 * w[c] + a1 * w[C + c] + bb[c];
    float xm = (xx > 0)      ? x[2 * (p - 1) + 1]  : 0.f;
    float xp = (xx < NX - 1) ? x[2 * (p + 1) + 1]  : 0.f;
    g_t0dx[p] = (xp - xm) * INV2DX;
    float zm = (z > 0)       ? x[2 * (p - NX) + 1] : 0.f;
    float zp = (z < NZ - 1)  ? x[2 * (p + NX) + 1] : 0.f;
    g_t0dz[p] = (zp - zm) * INV2DX;
}

// ---------------- fused forward DFT (x then z) per (b,c,s) slab ----------------
// dyn smem: slab f[96*98]@0(37632B) | s1re ull[1152]@37632 | s1im@46848 | sFxT u2[576]@56064
constexpr int RS = 98;                 // padded slab row stride (floats)
constexpr int SMEM_FWD = 65280;
__global__ void __launch_bounds__(256) k_fwd(int selIn, int Lprev) {
    extern __shared__ char smraw[];
    float* slab = (float*)smraw;
    ull*   s1re = (ull*)(smraw + 37632);
    ull*   s1im = (ull*)(smraw + 46848);
    ulonglong2* sFxT = (ulonglong2*)(smraw + 56064);
    int bid = blockIdx.x, tid = threadIdx.x;
    int c = (bid / NS) % C;
    float sc = 1.f, sh = 0.f;
    if (Lprev >= 0) { sc = g_scaleL[Lprev * C + c]; sh = g_shiftL[Lprev * C + c]; }
    const float* base = hbuf(selIn) + (size_t)bid * 9216;
    for (int i = tid; i < 9216; i += 256) {
        float v = base[i];
        if (Lprev >= 0) v = lrelu(fmaf(v, sc, sh));
        slab[(i / 96) * RS + (i % 96)] = v;
    }
    for (int i = tid; i < 576; i += 256) sFxT[i] = g_twFxT[i];
    __syncthreads();
    // stage 1: x-DFT real->complex, packed x-pairs; twiddle [xh][k] -> lanes contiguous
    for (int it = tid; it < 1152; it += 256) {
        int k = it % 12, z = it / 12;
        ull ar0 = 0, ar1 = 0, ai0 = 0, ai1 = 0;
        const float* row = slab + z * RS;
        const ulonglong2* twb = sFxT + k;
#pragma unroll 6
        for (int xh = 0; xh < 48; xh += 2) {
            ull v0 = *(const ull*)(row + 2 * xh);
            ull v1 = *(const ull*)(row + 2 * xh + 2);
            ulonglong2 t0 = twb[xh * 12], t1 = twb[(xh + 1) * 12];
            ar0 = fma2(v0, t0.x, ar0);
            ai0 = fma2(v0, t0.y, ai0);
            ar1 = fma2(v1, t1.x, ar1);
            ai1 = fma2(v1, t1.y, ai1);
        }
        float r0, r1, r2, r3, i0, i1, i2, i3;
        upk(ar0, r0, r1); upk(ar1, r2, r3); upk(ai0, i0, i1); upk(ai1, i2, i3);
        float re = (r0 + r1) + (r2 + r3), im = (i0 + i1) + (i2 + i3);
        s1re[it] = pk(re, re);
        s1im[it] = pk(im, im);
    }
    __syncthreads();
    // stage 2: z-DFT, 2 chains (twiddles from global, 3 distinct lines/warp -> L1)
    for (int it = tid; it < 288; it += 256) {
        int kx = it % 12, kz = it / 12;
        ull a0 = 0, a1 = 0;
        const ulonglong2* tw = g_twFzP + kz * 96;
#pragma unroll 4
        for (int z = 0; z < 96; z += 2) {
            ulonglong2 t0 = tw[z], t1 = tw[z + 1];
            a0 = fma2(s1re[z * 12 + kx], t0.x, a0);
            a0 = fma2(s1im[z * 12 + kx], t0.y, a0);
            a1 = fma2(s1re[(z + 1) * 12 + kx], t1.x, a1);
            a1 = fma2(s1im[(z + 1) * 12 + kx], t1.y, a1);
        }
        float u0, u1, v0, v1; upk(a0, u0, u1); upk(a1, v0, v1);
        g_S2[(size_t)bid * 288 + it] = make_float2(u0 + v0, u1 + v1);
    }
}

// ---------------- forward s-DFT ----------------
__global__ void k_f3() {
    int g = blockIdx.x * blockDim.x + threadIdx.x;
    int kx = g % KX, kzi = (g / KX) % KZ, ksi = (g / 288) % KS, bc = g / 4608;
    const float2* src = g_S2 + bc * NS * 288 + kzi * KX + kx;
    const float2* tw  = g_twFs + ksi * NS;
    float re0 = 0.f, im0 = 0.f, re1 = 0.f, im1 = 0.f;
#pragma unroll 4
    for (int s = 0; s < NS; s += 2) {
        float2 v0 = src[s * 288], t0 = tw[s];
        float2 v1 = src[(s + 1) * 288], t1 = tw[s + 1];
        re0 += v0.x * t0.x - v0.y * t0.y;
        im0 += v0.x * t0.y + v0.y * t0.x;
        re1 += v1.x * t1.x - v1.y * t1.y;
        im1 += v1.x * t1.y + v1.y * t1.x;
    }
    g_S3[(bc * KS + ksi) * 288 + kzi * KX + kx] = make_float2(re0 + re1, im0 + im1);
}

// ---------------- spectral multiply ----------------
__global__ void k_mul(int L, const float* __restrict__ spec) {
    int g = blockIdx.x * blockDim.x + threadIdx.x;
    int kx = g % KX, kzi = (g / KX) % KZ, ksi = (g / 288) % KS;
    int co = (g / 4608) % C, b = g / (4608 * C);
    int corner = (ksi >= M1 ? 1 : 0) + (kzi >= M2 ? 2 : 0);
    int k1 = (ksi >= M1) ? ksi - M1 : ksi;
    int k2 = (kzi >= M2) ? kzi - M2 : kzi;
    int wbase = ((((L * 4 + corner) * C) * C + co) * M1 + k1) * M2 + k2;
    wbase = wbase * M3 + kx;
    const int wstride = C * M1 * M2 * M3;
    const float2* xin = g_S3 + (b * C) * 4608 + ksi * 288 + kzi * KX + kx;
    const float2* wp  = (const float2*)spec + wbase;
    float re0 = 0.f, im0 = 0.f, re1 = 0.f, im1 = 0.f;
#pragma unroll 4
    for (int ci = 0; ci < C; ci += 2) {
        float2 a0 = xin[ci * 4608], w0 = wp[ci * wstride];
        float2 a1 = xin[(ci + 1) * 4608], w1 = wp[(ci + 1) * wstride];
        re0 += a0.x * w0.x - a0.y * w0.y;
        im0 += a0.x * w0.y + a0.y * w0.x;
        re1 += a1.x * w1.x - a1.y * w1.y;
        im1 += a1.x * w1.y + a1.y * w1.x;
    }
    g_G[g] = make_float2(re0 + re1, im0 + im1);
}

// ---------------- fused inverse DFT (s, z, x) per (b,c,s) slab ----------------
// dyn smem: sG float2[4608]@0 | T1re@36864 | T1im@39168 | T2re@41472 | T2im@50688 | sIxT u2[576]@59904
constexpr int SMEM_INV = 69120;
__global__ void __launch_bounds__(256) k_inv(int selOut) {
    extern __shared__ char smraw[];
    float2* sG  = (float2*)smraw;
    ull* T1re = (ull*)(smraw + 36864);
    ull* T1im = (ull*)(smraw + 39168);
    ull* T2re = (ull*)(smraw + 41472);
    ull* T2im = (ull*)(smraw + 50688);
    ulonglong2* sIxT = (ulonglong2*)(smraw + 59904);
    __shared__ float2 sTs[16];
    int bid = blockIdx.x, tid = threadIdx.x;
    int s = bid % NS, bc = bid / NS;
    for (int i = tid; i < 4608; i += 256) sG[i] = g_G[(size_t)bc * 4608 + i];
    for (int i = tid; i < 576;  i += 256) sIxT[i] = g_twIxT[i];
    if (tid < 16) sTs[tid] = g_twIs[s * 16 + tid];
    __syncthreads();
    for (int it = tid; it < 288; it += 256) {
        float re0 = 0.f, im0 = 0.f, re1 = 0.f, im1 = 0.f;
#pragma unroll
        for (int k = 0; k < 16; k += 2) {
            float2 v0 = sG[k * 288 + it], t0 = sTs[k];
            float2 v1 = sG[(k + 1) * 288 + it], t1 = sTs[k + 1];
            re0 += v0.x * t0.x - v0.y * t0.y;
            im0 += v0.x * t0.y + v0.y * t0.x;
            re1 += v1.x * t1.x - v1.y * t1.y;
            im1 += v1.x * t1.y + v1.y * t1.x;
        }
        float re = re0 + re1, im = im0 + im1;
        T1re[it] = pk(re, re); T1im[it] = pk(im, im);
    }
    __syncthreads();
    for (int it = tid; it < 1152; it += 256) {
        int kx = it % 12, z = it / 12;
        ull a0 = 0, a1 = 0;
        const ulonglong2* tw = g_twIzP + z * 24;
#pragma unroll
        for (int k = 0; k < 24; k += 2) {
            ulonglong2 t0 = tw[k], t1 = tw[k + 1];
            a0 = fma2(T1re[k * 12 + kx], t0.x, a0);
            a0 = fma2(T1im[k * 12 + kx], t0.y, a0);
            a1 = fma2(T1re[(k + 1) * 12 + kx], t1.x, a1);
            a1 = fma2(T1im[(k + 1) * 12 + kx], t1.y, a1);
        }
        float u0, u1, v0, v1; upk(a0, u0, u1); upk(a1, v0, v1);
        float re = u0 + v0, im = u1 + v1;
        T2re[it] = pk(re, re); T2im[it] = pk(im, im);
    }
    __syncthreads();
    // i3: twiddle [k][xh] -> lanes (xh) contiguous, conflict-free
    float* dst = hbuf(selOut) + (size_t)bid * 9216;
    for (int it = tid; it < 4608; it += 256) {
        int xh = it % 48, z = it / 48;
        ull a0 = 0, a1 = 0;
        const ulonglong2* twb = sIxT + xh;
#pragma unroll
        for (int k = 0; k < 12; k += 2) {
            ulonglong2 t0 = twb[k * 48], t1 = twb[(k + 1) * 48];
            a0 = fma2(T2re[z * 12 + k], t0.x, a0);
            a0 = fma2(T2im[z * 12 + k], t0.y, a0);
            a1 = fma2(T2re[z * 12 + k + 1], t1.x, a1);
            a1 = fma2(T2im[z * 12 + k + 1], t1.y, a1);
        }
        float u0, u1, v0, v1; upk(a0, u0, u1); upk(a1, v0, v1);
        *(float2*)(dst + z * 96 + 2 * xh) = make_float2(u0 + v0, u1 + v1);
    }
}

// ---------------- pointwise conv: OUT += W*act(BN(IN)) + b ----------------
__global__ void __launch_bounds__(256) k_w2(int selIn, int selOut, int Lprev, int L,
                                            const float* __restrict__ ww,
                                            const float* __restrict__ wb) {
    __shared__ ull sWP[C * 16];
    __shared__ float sB[32], sSc[32], sSh[32];
    int tid = threadIdx.x;
    for (int i = tid; i < 512; i += 256) {
        int cop = i & 15, ci = i >> 4;
        sWP[i] = pk(ww[L * 1024 + (2 * cop) * C + ci],
                    ww[L * 1024 + (2 * cop + 1) * C + ci]);
    }
    if (tid < 32) {
        sB[tid] = wb[L * C + tid];
        if (Lprev >= 0) { sSc[tid] = g_scaleL[Lprev * C + tid]; sSh[tid] = g_shiftL[Lprev * C + tid]; }
        else            { sSc[tid] = 1.f; sSh[tid] = 0.f; }
    }
    __syncthreads();
    int p = blockIdx.x * 256 + tid;
    int b = p / P, p0 = p % P;
    const float* h = hbuf(selIn) + b * C * P + p0;
    ull acc[16];
#pragma unroll
    for (int cop = 0; cop < 16; cop++) acc[cop] = pk(sB[2 * cop], sB[2 * cop + 1]);
    int useBn = (Lprev >= 0);
#pragma unroll
    for (int ci = 0; ci < 32; ci++) {
        float v = h[ci * P];
        if (useBn) v = lrelu(fmaf(v, sSc[ci], sSh[ci]));
        ull vp = pk(v, v);
        const ulonglong2* wr = (const ulonglong2*)&sWP[ci * 16];
#pragma unroll
        for (int q = 0; q < 8; q++) {
            ulonglong2 w = wr[q];
            acc[2 * q]     = fma2(vp, w.x, acc[2 * q]);
            acc[2 * q + 1] = fma2(vp, w.y, acc[2 * q + 1]);
        }
    }
    float* o = hbuf(selOut) + b * C * P + p0;
#pragma unroll
    for (int cop = 0; cop < 16; cop++) {
        float f0, f1; upk(acc[cop], f0, f1);
        o[(2 * cop) * P]     += f0;
        o[(2 * cop + 1) * P] += f1;
    }
}

// ---------------- batchnorm stats ----------------
__global__ void k_zero() {
    if (threadIdx.x < C) { g_sum[threadIdx.x] = 0.0; g_sq[threadIdx.x] = 0.0; }
}

__global__ void __launch_bounds__(256) k_stat(int selOut) {
    int bid = blockIdx.x;
    int c = (bid / (P / 4096)) % C;
    const float4* src = (const float4*)(hbuf(selOut) + (size_t)bid * 4096);
    float s = 0.f, q = 0.f;
#pragma unroll
    for (int r = 0; r < 4; r++) {
        float4 v = src[threadIdx.x + 256 * r];
        s += (v.x + v.y) + (v.z + v.w);
        q += (v.x * v.x + v.y * v.y) + (v.z * v.z + v.w * v.w);
    }
#pragma unroll
    for (int o = 16; o; o >>= 1) {
        s += __shfl_down_sync(0xffffffffu, s, o);
        q += __shfl_down_sync(0xffffffffu, q, o);
    }
    __shared__ float ws[8], wq[8];
    int wid = threadIdx.x >> 5, lane = threadIdx.x & 31;
    if (lane == 0) { ws[wid] = s; wq[wid] = q; }
    __syncthreads();
    if (threadIdx.x == 0) {
        float S = 0.f, Q = 0.f;
        for (int i = 0; i < 8; i++) { S += ws[i]; Q += wq[i]; }
        atomicAdd(&g_sum[c], (double)S);
        atomicAdd(&g_sq[c],  (double)Q);
    }
}

__global__ void k_fin(int L, const float* __restrict__ bg, const float* __restrict__ bb) {
    int c = threadIdx.x;
    if (c < C) {
        double n = (double)NPT;
        double m = g_sum[c] / n;
        double var = g_sq[c] / n - m * m;
        float sc = bg[L * C + c] * (float)(1.0 / sqrt(var + 1e-5));
        g_scaleL[L * C + c] = sc;
        g_shiftL[L * C + c] = bb[L * C + c] - (float)m * sc;
        g_sum[c] = 0.0;
        g_sq[c]  = 0.0;
    }
}

// ---------------- fused MLP + mask (f32x2, transposed weights, occ 2) ----------------
constexpr int OW1T = 0,      OB1 = 4096;
constexpr int OW2  = 4224,   OB2 = 12416;
constexpr int OW3T = 12480,  OB3 = 14528;
constexpr int OW4T = 14560,  OB4 = 16608;
constexpr int OW5T = 16672,  OB5 = 24864;
constexpr int OW7  = 24992,  OB7 = 25120;
constexpr int OSC  = 25121,  OSH = 25153;
constexpr int SMEM_MLP = 25185 * 4;

__global__ void __launch_bounds__(256, 2) k_mlp(
    const float* __restrict__ x,
    const float* __restrict__ w1, const float* __restrict__ b1,
    const float* __restrict__ w2, const float* __restrict__ b2,
    const float* __restrict__ w3, const float* __restrict__ b3,
    const float* __restrict__ w4, const float* __restrict__ b4,
    const float* __restrict__ w5, const float* __restrict__ b5,
    const float* __restrict__ w7, const float* __restrict__ b7,
    float* __restrict__ out) {
    extern __shared__ float sm[];
    int tid = threadIdx.x;
    for (int i = tid; i < 4096; i += 256) {
        int r = i >> 7, j = i & 127;
        sm[OW1T + j * 32 + r] = w1[i];
    }
    for (int i = tid; i < 128;  i += 256) sm[OB1 + i] = b1[i];
    for (int i = tid; i < 8192; i += 256) sm[OW2 + i] = w2[i];
    for (int i = tid; i < 64;   i += 256) sm[OB2 + i] = b2[i];
    for (int i = tid; i < 2048; i += 256) {
        int j = i >> 5, k = i & 31;
        sm[OW3T + k * 64 + j] = w3[i];
    }
    for (int i = tid; i < 32;   i += 256) sm[OB3 + i] = b3[i];
    for (int i = tid; i < 2048; i += 256) {
        int j = i >> 6, k = i & 63;
        sm[OW4T + k * 32 + j] = w4[i];
    }
    for (int i = tid; i < 64;   i += 256) sm[OB4 + i] = b4[i];
    for (int i = tid; i < 8192; i += 256) {
        int j = i >> 7, k = i & 127;
        sm[OW5T + k * 64 + j] = w5[i];
    }
    for (int i = tid; i < 128;  i += 256) sm[OB5 + i] = b5[i];
    for (int i = tid; i < 128;  i += 256) sm[OW7 + i] = w7[i];
    if (tid == 0) sm[OB7] = b7[0];
    if (tid < 32) { sm[OSC + tid] = g_scaleL[3 * C + tid]; sm[OSH + tid] = g_shiftL[3 * C + tid]; }
    __syncthreads();

    int p = blockIdx.x * 256 + tid;
    int b = p / P, p0 = p % P;
    const float* h = g_hA + b * C * P + p0;
    ull inl[16];
#pragma unroll
    for (int i = 0; i < 16; i++) {
        float v0 = lrelu(fmaf(h[(2 * i) * P],     sm[OSC + 2 * i],     sm[OSH + 2 * i]));
        float v1 = lrelu(fmaf(h[(2 * i + 1) * P], sm[OSC + 2 * i + 1], sm[OSH + 2 * i + 1]));
        inl[i] = pk(v0, v1);
    }

    ull a2[32];
#pragma unroll
    for (int k = 0; k < 32; k++) a2[k] = *(const ull*)&sm[OB2 + 2 * k];
#pragma unroll 1
    for (int j = 0; j < 128; j++) {
        ull c0 = 0, c1 = 0;
        const ulonglong2* wr = (const ulonglong2*)&sm[OW1T + j * 32];
#pragma unroll
        for (int m = 0; m < 8; m++) {
            ulonglong2 t = wr[m];
            c0 = fma2(inl[2 * m], t.x, c0);
            c1 = fma2(inl[2 * m + 1], t.y, c1);
        }
        float u0, u1, u2, u3;
        upk(c0, u0, u1); upk(c1, u2, u3);
        float a = lrelu((u0 + u1) + (u2 + u3) + sm[OB1 + j]);
        ull q = pk(a, a);
        const ulonglong2* r = (const ulonglong2*)&sm[OW2 + j * 64];
#pragma unroll
        for (int m = 0; m < 16; m++) {
            ulonglong2 t = r[m];
            a2[2 * m]     = fma2(q, t.x, a2[2 * m]);
            a2[2 * m + 1] = fma2(q, t.y, a2[2 * m + 1]);
        }
    }
#pragma unroll
    for (int k = 0; k < 32; k++) {
        float u, v; upk(a2[k], u, v);
        a2[k] = pk(lrelu(u), lrelu(v));
    }

    ull a3l[16];
#pragma unroll 1
    for (int k = 0; k < 32; k += 2) {
        ull c0 = 0, c1 = 0, d0 = 0, d1 = 0;
        const ulonglong2* r0 = (const ulonglong2*)&sm[OW3T + k * 64];
        const ulonglong2* r1 = (const ulonglong2*)&sm[OW3T + (k + 1) * 64];
#pragma unroll
        for (int m = 0; m < 16; m++) {
            ulonglong2 t0 = r0[m], t1 = r1[m];
            c0 = fma2(a2[2 * m], t0.x, c0);
            c1 = fma2(a2[2 * m + 1], t0.y, c1);
            d0 = fma2(a2[2 * m], t1.x, d0);
            d1 = fma2(a2[2 * m + 1], t1.y, d1);
        }
        float u0, u1, u2, u3, v0, v1, v2, v3;
        upk(c0, u0, u1); upk(c1, u2, u3); upk(d0, v0, v1); upk(d1, v2, v3);
        a3l[k >> 1] = pk(lrelu((u0 + u1) + (u2 + u3) + sm[OB3 + k]),
                         lrelu((v0 + v1) + (v2 + v3) + sm[OB3 + k + 1]));
    }

    ull a4l[32];
#pragma unroll 1
    for (int k = 0; k < 64; k += 2) {
        ull c0 = 0, c1 = 0, d0 = 0, d1 = 0;
        const ulonglong2* r0 = (const ulonglong2*)&sm[OW4T + k * 32];
        const ulonglong2* r1 = (const ulonglong2*)&sm[OW4T + (k + 1) * 32];
#pragma unroll
        for (int m = 0; m < 8; m++) {
            ulonglong2 t0 = r0[m], t1 = r1[m];
            c0 = fma2(a3l[2 * m], t0.x, c0);
            c1 = fma2(a3l[2 * m + 1], t0.y, c1);
            d0 = fma2(a3l[2 * m], t1.x, d0);
            d1 = fma2(a3l[2 * m + 1], t1.y, d1);
        }
        float u0, u1, u2, u3, v0, v1, v2, v3;
        upk(c0, u0, u1); upk(c1, u2, u3); upk(d0, v0, v1); upk(d1, v2, v3);
        a4l[k >> 1] = pk(lrelu((u0 + u1) + (u2 + u3) + sm[OB4 + k]),
                         lrelu((v0 + v1) + (v2 + v3) + sm[OB4 + k + 1]));
    }

    float tau = sm[OB7];
#pragma unroll 1
    for (int k = 0; k < 128; k += 2) {
        ull c0 = 0, c1 = 0, d0 = 0, d1 = 0;
        const ulonglong2* r0 = (const ulonglong2*)&sm[OW5T + k * 64];
        const ulonglong2* r1 = (const ulonglong2*)&sm[OW5T + (k + 1) * 64];
#pragma unroll
        for (int m = 0; m < 16; m++) {
            ulonglong2 t0 = r0[m], t1 = r1[m];
            c0 = fma2(a4l[2 * m], t0.x, c0);
            c1 = fma2(a4l[2 * m + 1], t0.y, c1);
            d0 = fma2(a4l[2 * m], t1.x, d0);
            d1 = fma2(a4l[2 * m + 1], t1.y, d1);
        }
        float u0, u1, u2, u3, v0, v1, v2, v3;
        upk(c0, u0, u1); upk(c1, u2, u3); upk(d0, v0, v1); upk(d1, v2, v3);
        float a5a = lrelu((u0 + u1) + (u2 + u3) + sm[OB5 + k]);
        float a5b = lrelu((v0 + v1) + (v2 + v3) + sm[OB5 + k + 1]);
        tau += a5a * sm[OW7 + k] + a5b * sm[OW7 + k + 1];
    }

    float T0 = x[2 * p + 1];
    int z = (p0 / NX) % NZ;
    float mask = (z < 2) ? 0.f : ((T0 < 0.01f) ? T0 : 1.f);
    out[p] = tau * mask;
}

// ---------------- loss ----------------
__global__ void k_loss(const float* __restrict__ y, float* __restrict__ out) {
    int p = blockIdx.x * blockDim.x + threadIdx.x;
    if (p >= NPT) return;
    int p0 = p % P;
    int xx = p0 % NX;
    int z = (p0 / NX) % NZ;
    const float* tau = out;
    float tm = (xx > 0)      ? tau[p - 1]  : 0.f;
    float tp = (xx < NX - 1) ? tau[p + 1]  : 0.f;
    float dx = (tp - tm) * INV2DX + g_t0dx[p];
    float zm = (z > 0)       ? tau[p - NX] : 0.f;
    float zp = (z < NZ - 1)  ? tau[p + NX] : 0.f;
    float dz = (zp - zm) * INV2DX + g_t0dz[p];
    out[NPT + p] = dx * dx + dz * dz - y[p];
}

// ---------------- launch ----------------
extern "C" void kernel_launch(void* const* d_in, const int* in_sizes, int n_in,
                              void* d_out, int out_size) {
    const float* x      = (const float*)d_in[0];
    const float* y      = (const float*)d_in[1];
    const float* fc0_w  = (const float*)d_in[2];
    const float* fc0_b  = (const float*)d_in[3];
    const float* spec_w = (const float*)d_in[4];
    const float* w_w    = (const float*)d_in[5];
    const float* w_b    = (const float*)d_in[6];
    const float* bn_g   = (const float*)d_in[7];
    const float* bn_b   = (const float*)d_in[8];
    const float* fc1_w  = (const float*)d_in[9];
    const float* fc1_b  = (const float*)d_in[10];
    const float* fc2_w  = (const float*)d_in[11];
    const float* fc2_b  = (const float*)d_in[12];
    const float* fc3_w  = (const float*)d_in[13];
    const float* fc3_b  = (const float*)d_in[14];
    const float* fc4_w  = (const float*)d_in[15];
    const float* fc4_b  = (const float*)d_in[16];
    const float* fc5_w  = (const float*)d_in[17];
    const float* fc5_b  = (const float*)d_in[18];
    const float* fc7_w  = (const float*)d_in[19];
    const float* fc7_b  = (const float*)d_in[20];
    float* out = (float*)d_out;

    cudaFuncSetAttribute(k_fwd, cudaFuncAttributeMaxDynamicSharedMemorySize, SMEM_FWD);
    cudaFuncSetAttribute(k_inv, cudaFuncAttributeMaxDynamicSharedMemorySize, SMEM_INV);
    cudaFuncSetAttribute(k_mlp, cudaFuncAttributeMaxDynamicSharedMemorySize, SMEM_MLP);

    k_init_tw<<<9, 256>>>();
    k_zero<<<1, 32>>>();
    k_fc0t0<<<NPT / 256, 256>>>(x, fc0_w, fc0_b);

    for (int L = 0; L < 4; L++) {
        int in = L & 1, outb = 1 - in, Lp = L - 1;
        k_fwd<<<B * C * NS, 256, SMEM_FWD>>>(in, Lp);
        k_f3<<<(B * C * KS * KZ * KX) / 256, 256>>>();
        k_mul<<<(B * C * KS * KZ * KX) / 256, 256>>>(L, spec_w);
        k_inv<<<B * C * NS, 256, SMEM_INV>>>(outb);
        k_w2<<<NPT / 256, 256>>>(in, outb, Lp, L, w_w, w_b);
        k_stat<<<B * C * (P / 4096), 256>>>(outb);
        k_fin<<<1, 32>>>(L, bn_g, bn_b);
    }

    k_mlp<<<NPT / 256, 256, SMEM_MLP>>>(x,
        fc1_w, fc1_b, fc2_w, fc2_b, fc3_w, fc3_b,
        fc4_w, fc4_b, fc5_w, fc5_b, fc7_w, fc7_b, out);
    k_loss<<<NPT / 256, 256>>>(y, out);
}

// round 14
// speedup vs baseline: 1.9316x; 1.1332x over previous
#include <cuda_runtime.h>
#include <math.h>
#include <stdint.h>

typedef unsigned long long ull;

constexpr int B  = 2;
constexpr int C  = 32;
constexpr int NS = 32;
constexpr int NZ = 96;
constexpr int NX = 96;
constexpr int P  = NS * NZ * NX;
constexpr int NPT = B * P;
constexpr int M1 = 8, M2 = 12, M3 = 12;
constexpr int KS = 16, KZ = 24, KX = 12;
constexpr float SLOPE = 0.1f;
constexpr float INV2DX = 50.0f;

// ---------------- scratch ----------------
__device__ float  g_hA[B * C * P];
__device__ float  g_hB[B * C * P];
__device__ float2 g_S2[B * C * NS * KZ * KX];
__device__ float2 g_S3[B * C * KS * KZ * KX];
__device__ float2 g_G [B * C * KS * KZ * KX];
__device__ float  g_t0dx[NPT];
__device__ float  g_t0dz[NPT];
__device__ double g_sum[C];
__device__ double g_sq[C];
__device__ float  g_scaleL[4 * C];
__device__ float  g_shiftL[4 * C];

// packed twiddles (lane-varying index contiguous)
__device__ ulonglong2 g_twFxT[48 * KX];   // [xh][k]
__device__ ulonglong2 g_twFzP[KZ * NZ];   // [kz][z]
__device__ ulonglong2 g_twIzP[NZ * KZ];   // [z][k]
__device__ ulonglong2 g_twIxT[KX * 48];   // [k][xh]
__device__ float2 g_twFs[KS * NS];
__device__ float2 g_twIs[NS * KS];

__device__ __forceinline__ float lrelu(float v) { return v > 0.f ? v : SLOPE * v; }
__device__ __forceinline__ float* hbuf(int s) { return s ? g_hB : g_hA; }
__device__ __forceinline__ ull pk(float a, float b) {
    ull r; asm("mov.b64 %0,{%1,%2};" : "=l"(r) : "f"(a), "f"(b)); return r;
}
__device__ __forceinline__ void upk(ull v, float& a, float& b) {
    asm("mov.b64 {%0,%1},%2;" : "=f"(a), "=f"(b) : "l"(v));
}
__device__ __forceinline__ ull fma2(ull a, ull b, ull c) {
    ull d; asm("fma.rn.f32x2 %0,%1,%2,%3;" : "=l"(d) : "l"(a), "l"(b), "l"(c)); return d;
}

// ---------------- twiddle init ----------------
__global__ void k_init_tw() {
    int t = blockIdx.x * blockDim.x + threadIdx.x;
    if (t < 576) {                       // FxT: [xh][k]
        int xh = t / 12, k = t % 12;
        double s0, c0, s1, c1;
        sincospi(2.0 * double((k * (2 * xh)) % NX) / NX, &s0, &c0);
        sincospi(2.0 * double((k * (2 * xh + 1)) % NX) / NX, &s1, &c1);
        g_twFxT[t].x = pk((float)(c0 / NX), (float)(c1 / NX));
        g_twFxT[t].y = pk((float)(-s0 / NX), (float)(-s1 / NX));
    }
    if (t < 2304) {
        int kzi = t / 96, z = t % 96;
        int kz = (kzi < M2) ? kzi : kzi + (NZ - KZ);
        double s, c; sincospi(2.0 * double((kz * z) % NZ) / NZ, &s, &c);
        float tx = (float)(c / NZ), ty = (float)(-s / NZ);
        g_twFzP[t].x = pk(tx, ty); g_twFzP[t].y = pk(-ty, tx);
    }
    if (t < 2304) {
        int z = t / 24, k = t % 24;
        int kz = (k < M2) ? k : k + (NZ - KZ);
        double s, c; sincospi(2.0 * double((kz * z) % NZ) / NZ, &s, &c);
        float tx = (float)c, ty = (float)s;
        g_twIzP[t].x = pk(tx, ty); g_twIzP[t].y = pk(-ty, tx);
    }
    if (t < 576) {                       // IxT: [k][xh]
        int k = t / 48, xh = t % 48;
        double s0, c0, s1, c1;
        sincospi(2.0 * double((k * (2 * xh)) % NX) / NX, &s0, &c0);
        sincospi(2.0 * double((k * (2 * xh + 1)) % NX) / NX, &s1, &c1);
        g_twIxT[t].x = pk((float)c0, (float)c1);
        g_twIxT[t].y = pk((float)(-s0), (float)(-s1));
    }
    if (t < 512) {
        int ksi = t / 32, s0i = t % 32;
        int ks = (ksi < M1) ? ksi : ksi + (NS - KS);
        double s, c; sincospi(2.0 * double((ks * s0i) % NS) / NS, &s, &c);
        g_twFs[t] = make_float2((float)(c / NS), (float)(-s / NS));
    }
    if (t < 512) {
        int s0i = t / 16, k = t % 16;
        int ks = (k < M1) ? k : k + (NS - KS);
        double s, c; sincospi(2.0 * double((ks * s0i) % NS) / NS, &s, &c);
        g_twIs[t] = make_float2((float)c, (float)s);
    }
}

// ---------------- fc0 + T0 derivatives ----------------
__global__ void k_fc0t0(const float* __restrict__ x, const float* __restrict__ w,
                        const float* __restrict__ bb) {
    int p = blockIdx.x * blockDim.x + threadIdx.x;
    if (p >= NPT) return;
    int b = p / P, p0 = p % P;
    int xx = p0 % NX;
    int z  = (p0 / NX) % NZ;
    float a0 = x[2 * p], a1 = x[2 * p + 1];
#pragma unroll
    for (int c = 0; c < C; c++)
        g_hA[(b * C + c) * P + p0] = a0 * w[c] + a1 * w[C + c] + bb[c];
    float xm = (xx > 0)      ? x[2 * (p - 1) + 1]  : 0.f;
    float xp = (xx < NX - 1) ? x[2 * (p + 1) + 1]  : 0.f;
    g_t0dx[p] = (xp - xm) * INV2DX;
    float zm = (z > 0)       ? x[2 * (p - NX) + 1] : 0.f;
    float zp = (z < NZ - 1)  ? x[2 * (p + NX) + 1] : 0.f;
    g_t0dz[p] = (zp - zm) * INV2DX;
}

// ---------------- fused forward DFT (x then z) per (b,c,s) slab ----------------
// dyn smem: slab f[96*98]@0(37632) | s1 float2[1152]@37632(9216) | sFxT u2[576]@46848(9216)
constexpr int RS = 98;
constexpr int SMEM_FWD = 56064;
__global__ void __launch_bounds__(256) k_fwd(int selIn, int Lprev) {
    extern __shared__ char smraw[];
    float* slab = (float*)smraw;
    float2* s1  = (float2*)(smraw + 37632);
    ulonglong2* sFxT = (ulonglong2*)(smraw + 46848);
    int bid = blockIdx.x, tid = threadIdx.x;
    int c = (bid / NS) % C;
    float sc = 1.f, sh = 0.f;
    if (Lprev >= 0) { sc = g_scaleL[Lprev * C + c]; sh = g_shiftL[Lprev * C + c]; }
    const float* base = hbuf(selIn) + (size_t)bid * 9216;
    for (int i = tid; i < 9216; i += 256) {
        float v = base[i];
        if (Lprev >= 0) v = lrelu(fmaf(v, sc, sh));
        slab[(i / 96) * RS + (i % 96)] = v;
    }
    for (int i = tid; i < 576; i += 256) sFxT[i] = g_twFxT[i];
    __syncthreads();
    // stage 1: x-DFT, z-pairs per thread (twiddle shared), 8 chains
    for (int it = tid; it < 576; it += 256) {
        int k = it % 12, z = (it / 12) * 2;
        const float* rowA = slab + z * RS;
        const float* rowB = rowA + RS;
        const ulonglong2* twb = sFxT + k;
        ull arA0 = 0, aiA0 = 0, arB0 = 0, aiB0 = 0;
        ull arA1 = 0, aiA1 = 0, arB1 = 0, aiB1 = 0;
#pragma unroll 6
        for (int xh = 0; xh < 48; xh += 2) {
            ull vA0 = *(const ull*)(rowA + 2 * xh);
            ull vA1 = *(const ull*)(rowA + 2 * xh + 2);
            ull vB0 = *(const ull*)(rowB + 2 * xh);
            ull vB1 = *(const ull*)(rowB + 2 * xh + 2);
            ulonglong2 t0 = twb[xh * 12], t1 = twb[(xh + 1) * 12];
            arA0 = fma2(vA0, t0.x, arA0);
            aiA0 = fma2(vA0, t0.y, aiA0);
            arB0 = fma2(vB0, t0.x, arB0);
            aiB0 = fma2(vB0, t0.y, aiB0);
            arA1 = fma2(vA1, t1.x, arA1);
            aiA1 = fma2(vA1, t1.y, aiA1);
            arB1 = fma2(vB1, t1.x, arB1);
            aiB1 = fma2(vB1, t1.y, aiB1);
        }
        float a, b2, c2, d;
        upk(arA0, a, b2); upk(arA1, c2, d); float reA = (a + b2) + (c2 + d);
        upk(aiA0, a, b2); upk(aiA1, c2, d); float imA = (a + b2) + (c2 + d);
        upk(arB0, a, b2); upk(arB1, c2, d); float reB = (a + b2) + (c2 + d);
        upk(aiB0, a, b2); upk(aiB1, c2, d); float imB = (a + b2) + (c2 + d);
        s1[z * 12 + k]       = make_float2(reA, imA);
        s1[(z + 1) * 12 + k] = make_float2(reB, imB);
    }
    __syncthreads();
    // stage 2: z-DFT, compact s1 reads (pack at use)
    for (int it = tid; it < 288; it += 256) {
        int kx = it % 12, kz = it / 12;
        ull a0 = 0, a1 = 0;
        const ulonglong2* tw = g_twFzP + kz * 96;
#pragma unroll 4
        for (int z = 0; z < 96; z += 2) {
            float2 v0 = s1[z * 12 + kx], v1 = s1[(z + 1) * 12 + kx];
            ulonglong2 t0 = tw[z], t1 = tw[z + 1];
            a0 = fma2(pk(v0.x, v0.x), t0.x, a0);
            a0 = fma2(pk(v0.y, v0.y), t0.y, a0);
            a1 = fma2(pk(v1.x, v1.x), t1.x, a1);
            a1 = fma2(pk(v1.y, v1.y), t1.y, a1);
        }
        float u0, u1, v0f, v1f; upk(a0, u0, u1); upk(a1, v0f, v1f);
        g_S2[(size_t)bid * 288 + it] = make_float2(u0 + v0f, u1 + v1f);
    }
}

// ---------------- forward s-DFT ----------------
__global__ void k_f3() {
    int g = blockIdx.x * blockDim.x + threadIdx.x;
    int kx = g % KX, kzi = (g / KX) % KZ, ksi = (g / 288) % KS, bc = g / 4608;
    const float2* src = g_S2 + bc * NS * 288 + kzi * KX + kx;
    const float2* tw  = g_twFs + ksi * NS;
    float re0 = 0.f, im0 = 0.f, re1 = 0.f, im1 = 0.f;
#pragma unroll 4
    for (int s = 0; s < NS; s += 2) {
        float2 v0 = src[s * 288], t0 = tw[s];
        float2 v1 = src[(s + 1) * 288], t1 = tw[s + 1];
        re0 += v0.x * t0.x - v0.y * t0.y;
        im0 += v0.x * t0.y + v0.y * t0.x;
        re1 += v1.x * t1.x - v1.y * t1.y;
        im1 += v1.x * t1.y + v1.y * t1.x;
    }
    g_S3[(bc * KS + ksi) * 288 + kzi * KX + kx] = make_float2(re0 + re1, im0 + im1);
}

// ---------------- spectral multiply ----------------
__global__ void k_mul(int L, const float* __restrict__ spec) {
    int g = blockIdx.x * blockDim.x + threadIdx.x;
    int kx = g % KX, kzi = (g / KX) % KZ, ksi = (g / 288) % KS;
    int co = (g / 4608) % C, b = g / (4608 * C);
    int corner = (ksi >= M1 ? 1 : 0) + (kzi >= M2 ? 2 : 0);
    int k1 = (ksi >= M1) ? ksi - M1 : ksi;
    int k2 = (kzi >= M2) ? kzi - M2 : kzi;
    int wbase = ((((L * 4 + corner) * C) * C + co) * M1 + k1) * M2 + k2;
    wbase = wbase * M3 + kx;
    const int wstride = C * M1 * M2 * M3;
    const float2* xin = g_S3 + (b * C) * 4608 + ksi * 288 + kzi * KX + kx;
    const float2* wp  = (const float2*)spec + wbase;
    float re0 = 0.f, im0 = 0.f, re1 = 0.f, im1 = 0.f;
#pragma unroll 4
    for (int ci = 0; ci < C; ci += 2) {
        float2 a0 = xin[ci * 4608], w0 = wp[ci * wstride];
        float2 a1 = xin[(ci + 1) * 4608], w1 = wp[(ci + 1) * wstride];
        re0 += a0.x * w0.x - a0.y * w0.y;
        im0 += a0.x * w0.y + a0.y * w0.x;
        re1 += a1.x * w1.x - a1.y * w1.y;
        im1 += a1.x * w1.y + a1.y * w1.x;
    }
    g_G[g] = make_float2(re0 + re1, im0 + im1);
}

// ---------------- fused inverse DFT (s, z, x) per (b,c,s) slab ----------------
// dyn smem: T1re ull[288]@0 | T1im@2304 | T2re ull[1152]@4608 | T2im@13824 | sIxT u2[576]@23040 -> 32256
constexpr int SMEM_INV = 32256;
__global__ void __launch_bounds__(256) k_inv(int selOut) {
    extern __shared__ char smraw[];
    ull* T1re = (ull*)smraw;
    ull* T1im = (ull*)(smraw + 2304);
    ull* T2re = (ull*)(smraw + 4608);
    ull* T2im = (ull*)(smraw + 13824);
    ulonglong2* sIxT = (ulonglong2*)(smraw + 23040);
    __shared__ float2 sTs[16];
    int bid = blockIdx.x, tid = threadIdx.x;
    int s = bid % NS, bc = bid / NS;
    for (int i = tid; i < 576;  i += 256) sIxT[i] = g_twIxT[i];
    if (tid < 16) sTs[tid] = g_twIs[s * 16 + tid];
    __syncthreads();
    // i1: read g_G directly from global (each element used once; L2-resident across s-blocks)
    const float2* Gp = g_G + (size_t)bc * 4608;
    for (int it = tid; it < 288; it += 256) {
        float re0 = 0.f, im0 = 0.f, re1 = 0.f, im1 = 0.f;
#pragma unroll
        for (int k = 0; k < 16; k += 2) {
            float2 v0 = Gp[k * 288 + it], t0 = sTs[k];
            float2 v1 = Gp[(k + 1) * 288 + it], t1 = sTs[k + 1];
            re0 += v0.x * t0.x - v0.y * t0.y;
            im0 += v0.x * t0.y + v0.y * t0.x;
            re1 += v1.x * t1.x - v1.y * t1.y;
            im1 += v1.x * t1.y + v1.y * t1.x;
        }
        float re = re0 + re1, im = im0 + im1;
        T1re[it] = pk(re, re); T1im[it] = pk(im, im);
    }
    __syncthreads();
    // i2: 24 -> 96 along z
    for (int it = tid; it < 1152; it += 256) {
        int kx = it % 12, z = it / 12;
        ull a0 = 0, a1 = 0;
        const ulonglong2* tw = g_twIzP + z * 24;
#pragma unroll
        for (int k = 0; k < 24; k += 2) {
            ulonglong2 t0 = tw[k], t1 = tw[k + 1];
            a0 = fma2(T1re[k * 12 + kx], t0.x, a0);
            a0 = fma2(T1im[k * 12 + kx], t0.y, a0);
            a1 = fma2(T1re[(k + 1) * 12 + kx], t1.x, a1);
            a1 = fma2(T1im[(k + 1) * 12 + kx], t1.y, a1);
        }
        float u0, u1, v0, v1; upk(a0, u0, u1); upk(a1, v0, v1);
        float re = u0 + v0, im = u1 + v1;
        T2re[it] = pk(re, re); T2im[it] = pk(im, im);
    }
    __syncthreads();
    // i3: z-pairs per thread (twiddle shared), lanes xh contiguous
    float* dst = hbuf(selOut) + (size_t)bid * 9216;
    for (int it = tid; it < 2304; it += 256) {
        int xh = it % 48, z = (it / 48) * 2;
        ull aA0 = 0, aA1 = 0, aB0 = 0, aB1 = 0;
        const ulonglong2* twb = sIxT + xh;
#pragma unroll
        for (int k = 0; k < 12; k += 2) {
            ulonglong2 t0 = twb[k * 48], t1 = twb[(k + 1) * 48];
            aA0 = fma2(T2re[z * 12 + k],       t0.x, aA0);
            aA0 = fma2(T2im[z * 12 + k],       t0.y, aA0);
            aA1 = fma2(T2re[z * 12 + k + 1],   t1.x, aA1);
            aA1 = fma2(T2im[z * 12 + k + 1],   t1.y, aA1);
            aB0 = fma2(T2re[(z + 1) * 12 + k],     t0.x, aB0);
            aB0 = fma2(T2im[(z + 1) * 12 + k],     t0.y, aB0);
            aB1 = fma2(T2re[(z + 1) * 12 + k + 1], t1.x, aB1);
            aB1 = fma2(T2im[(z + 1) * 12 + k + 1], t1.y, aB1);
        }
        float u0, u1, v0, v1;
        upk(aA0, u0, u1); upk(aA1, v0, v1);
        *(float2*)(dst + z * 96 + 2 * xh) = make_float2(u0 + v0, u1 + v1);
        upk(aB0, u0, u1); upk(aB1, v0, v1);
        *(float2*)(dst + (z + 1) * 96 + 2 * xh) = make_float2(u0 + v0, u1 + v1);
    }
}

// ---------------- pointwise conv: OUT += W*act(BN(IN)) + b ----------------
__global__ void __launch_bounds__(256) k_w2(int selIn, int selOut, int Lprev, int L,
                                            const float* __restrict__ ww,
                                            const float* __restrict__ wb) {
    __shared__ ull sWP[C * 16];
    __shared__ float sB[32], sSc[32], sSh[32];
    int tid = threadIdx.x;
    for (int i = tid; i < 512; i += 256) {
        int cop = i & 15, ci = i >> 4;
        sWP[i] = pk(ww[L * 1024 + (2 * cop) * C + ci],
                    ww[L * 1024 + (2 * cop + 1) * C + ci]);
    }
    if (tid < 32) {
        sB[tid] = wb[L * C + tid];
        if (Lprev >= 0) { sSc[tid] = g_scaleL[Lprev * C + tid]; sSh[tid] = g_shiftL[Lprev * C + tid]; }
        else            { sSc[tid] = 1.f; sSh[tid] = 0.f; }
    }
    __syncthreads();
    int p = blockIdx.x * 256 + tid;
    int b = p / P, p0 = p % P;
    const float* h = hbuf(selIn) + b * C * P + p0;
    ull acc[16];
#pragma unroll
    for (int cop = 0; cop < 16; cop++) acc[cop] = pk(sB[2 * cop], sB[2 * cop + 1]);
    int useBn = (Lprev >= 0);
#pragma unroll
    for (int ci = 0; ci < 32; ci++) {
        float v = h[ci * P];
        if (useBn) v = lrelu(fmaf(v, sSc[ci], sSh[ci]));
        ull vp = pk(v, v);
        const ulonglong2* wr = (const ulonglong2*)&sWP[ci * 16];
#pragma unroll
        for (int q = 0; q < 8; q++) {
            ulonglong2 w = wr[q];
            acc[2 * q]     = fma2(vp, w.x, acc[2 * q]);
            acc[2 * q + 1] = fma2(vp, w.y, acc[2 * q + 1]);
        }
    }
    float* o = hbuf(selOut) + b * C * P + p0;
#pragma unroll
    for (int cop = 0; cop < 16; cop++) {
        float f0, f1; upk(acc[cop], f0, f1);
        o[(2 * cop) * P]     += f0;
        o[(2 * cop + 1) * P] += f1;
    }
}

// ---------------- batchnorm stats ----------------
__global__ void k_zero() {
    if (threadIdx.x < C) { g_sum[threadIdx.x] = 0.0; g_sq[threadIdx.x] = 0.0; }
}

__global__ void __launch_bounds__(256) k_stat(int selOut) {
    int bid = blockIdx.x;
    int c = (bid / (P / 4096)) % C;
    const float4* src = (const float4*)(hbuf(selOut) + (size_t)bid * 4096);
    float s = 0.f, q = 0.f;
#pragma unroll
    for (int r = 0; r < 4; r++) {
        float4 v = src[threadIdx.x + 256 * r];
        s += (v.x + v.y) + (v.z + v.w);
        q += (v.x * v.x + v.y * v.y) + (v.z * v.z + v.w * v.w);
    }
#pragma unroll
    for (int o = 16; o; o >>= 1) {
        s += __shfl_down_sync(0xffffffffu, s, o);
        q += __shfl_down_sync(0xffffffffu, q, o);
    }
    __shared__ float ws[8], wq[8];
    int wid = threadIdx.x >> 5, lane = threadIdx.x & 31;
    if (lane == 0) { ws[wid] = s; wq[wid] = q; }
    __syncthreads();
    if (threadIdx.x == 0) {
        float S = 0.f, Q = 0.f;
        for (int i = 0; i < 8; i++) { S += ws[i]; Q += wq[i]; }
        atomicAdd(&g_sum[c], (double)S);
        atomicAdd(&g_sq[c],  (double)Q);
    }
}

__global__ void k_fin(int L, const float* __restrict__ bg, const float* __restrict__ bb) {
    int c = threadIdx.x;
    if (c < C) {
        double n = (double)NPT;
        double m = g_sum[c] / n;
        double var = g_sq[c] / n - m * m;
        float sc = bg[L * C + c] * (float)(1.0 / sqrt(var + 1e-5));
        g_scaleL[L * C + c] = sc;
        g_shiftL[L * C + c] = bb[L * C + c] - (float)m * sc;
        g_sum[c] = 0.0;
        g_sq[c]  = 0.0;
    }
}

// ---------------- fused MLP + mask (f32x2, transposed weights, occ 2) ----------------
constexpr int OW1T = 0,      OB1 = 4096;
constexpr int OW2  = 4224,   OB2 = 12416;
constexpr int OW3T = 12480,  OB3 = 14528;
constexpr int OW4T = 14560,  OB4 = 16608;
constexpr int OW5T = 16672,  OB5 = 24864;
constexpr int OW7  = 24992,  OB7 = 25120;
constexpr int OSC  = 25121,  OSH = 25153;
constexpr int SMEM_MLP = 25185 * 4;

__global__ void __launch_bounds__(256, 2) k_mlp(
    const float* __restrict__ x,
    const float* __restrict__ w1, const float* __restrict__ b1,
    const float* __restrict__ w2, const float* __restrict__ b2,
    const float* __restrict__ w3, const float* __restrict__ b3,
    const float* __restrict__ w4, const float* __restrict__ b4,
    const float* __restrict__ w5, const float* __restrict__ b5,
    const float* __restrict__ w7, const float* __restrict__ b7,
    float* __restrict__ out) {
    extern __shared__ float sm[];
    int tid = threadIdx.x;
    for (int i = tid; i < 4096; i += 256) {
        int r = i >> 7, j = i & 127;
        sm[OW1T + j * 32 + r] = w1[i];
    }
    for (int i = tid; i < 128;  i += 256) sm[OB1 + i] = b1[i];
    for (int i = tid; i < 8192; i += 256) sm[OW2 + i] = w2[i];
    for (int i = tid; i < 64;   i += 256) sm[OB2 + i] = b2[i];
    for (int i = tid; i < 2048; i += 256) {
        int j = i >> 5, k = i & 31;
        sm[OW3T + k * 64 + j] = w3[i];
    }
    for (int i = tid; i < 32;   i += 256) sm[OB3 + i] = b3[i];
    for (int i = tid; i < 2048; i += 256) {
        int j = i >> 6, k = i & 63;
        sm[OW4T + k * 32 + j] = w4[i];
    }
    for (int i = tid; i < 64;   i += 256) sm[OB4 + i] = b4[i];
    for (int i = tid; i < 8192; i += 256) {
        int j = i >> 7, k = i & 127;
        sm[OW5T + k * 64 + j] = w5[i];
    }
    for (int i = tid; i < 128;  i += 256) sm[OB5 + i] = b5[i];
    for (int i = tid; i < 128;  i += 256) sm[OW7 + i] = w7[i];
    if (tid == 0) sm[OB7] = b7[0];
    if (tid < 32) { sm[OSC + tid] = g_scaleL[3 * C + tid]; sm[OSH + tid] = g_shiftL[3 * C + tid]; }
    __syncthreads();

    int p = blockIdx.x * 256 + tid;
    int b = p / P, p0 = p % P;
    const float* h = g_hA + b * C * P + p0;
    ull inl[16];
#pragma unroll
    for (int i = 0; i < 16; i++) {
        float v0 = lrelu(fmaf(h[(2 * i) * P],     sm[OSC + 2 * i],     sm[OSH + 2 * i]));
        float v1 = lrelu(fmaf(h[(2 * i + 1) * P], sm[OSC + 2 * i + 1], sm[OSH + 2 * i + 1]));
        inl[i] = pk(v0, v1);
    }

    ull a2[32];
#pragma unroll
    for (int k = 0; k < 32; k++) a2[k] = *(const ull*)&sm[OB2 + 2 * k];
#pragma unroll 1
    for (int j = 0; j < 128; j++) {
        ull c0 = 0, c1 = 0;
        const ulonglong2* wr = (const ulonglong2*)&sm[OW1T + j * 32];
#pragma unroll
        for (int m = 0; m < 8; m++) {
            ulonglong2 t = wr[m];
            c0 = fma2(inl[2 * m], t.x, c0);
            c1 = fma2(inl[2 * m + 1], t.y, c1);
        }
        float u0, u1, u2, u3;
        upk(c0, u0, u1); upk(c1, u2, u3);
        float a = lrelu((u0 + u1) + (u2 + u3) + sm[OB1 + j]);
        ull q = pk(a, a);
        const ulonglong2* r = (const ulonglong2*)&sm[OW2 + j * 64];
#pragma unroll
        for (int m = 0; m < 16; m++) {
            ulonglong2 t = r[m];
            a2[2 * m]     = fma2(q, t.x, a2[2 * m]);
            a2[2 * m + 1] = fma2(q, t.y, a2[2 * m + 1]);
        }
    }
#pragma unroll
    for (int k = 0; k < 32; k++) {
        float u, v; upk(a2[k], u, v);
        a2[k] = pk(lrelu(u), lrelu(v));
    }

    ull a3l[16];
#pragma unroll 1
    for (int k = 0; k < 32; k += 2) {
        ull c0 = 0, c1 = 0, d0 = 0, d1 = 0;
        const ulonglong2* r0 = (const ulonglong2*)&sm[OW3T + k * 64];
        const ulonglong2* r1 = (const ulonglong2*)&sm[OW3T + (k + 1) * 64];
#pragma unroll
        for (int m = 0; m < 16; m++) {
            ulonglong2 t0 = r0[m], t1 = r1[m];
            c0 = fma2(a2[2 * m], t0.x, c0);
            c1 = fma2(a2[2 * m + 1], t0.y, c1);
            d0 = fma2(a2[2 * m], t1.x, d0);
            d1 = fma2(a2[2 * m + 1], t1.y, d1);
        }
        float u0, u1, u2, u3, v0, v1, v2, v3;
        upk(c0, u0, u1); upk(c1, u2, u3); upk(d0, v0, v1); upk(d1, v2, v3);
        a3l[k >> 1] = pk(lrelu((u0 + u1) + (u2 + u3) + sm[OB3 + k]),
                         lrelu((v0 + v1) + (v2 + v3) + sm[OB3 + k + 1]));
    }

    ull a4l[32];
#pragma unroll 1
    for (int k = 0; k < 64; k += 2) {
        ull c0 = 0, c1 = 0, d0 = 0, d1 = 0;
        const ulonglong2* r0 = (const ulonglong2*)&sm[OW4T + k * 32];
        const ulonglong2* r1 = (const ulonglong2*)&sm[OW4T + (k + 1) * 32];
#pragma unroll
        for (int m = 0; m < 8; m++) {
            ulonglong2 t0 = r0[m], t1 = r1[m];
            c0 = fma2(a3l[2 * m], t0.x, c0);
            c1 = fma2(a3l[2 * m + 1], t0.y, c1);
            d0 = fma2(a3l[2 * m], t1.x, d0);
            d1 = fma2(a3l[2 * m + 1], t1.y, d1);
        }
        float u0, u1, u2, u3, v0, v1, v2, v3;
        upk(c0, u0, u1); upk(c1, u2, u3); upk(d0, v0, v1); upk(d1, v2, v3);
        a4l[k >> 1] = pk(lrelu((u0 + u1) + (u2 + u3) + sm[OB4 + k]),
                         lrelu((v0 + v1) + (v2 + v3) + sm[OB4 + k + 1]));
    }

    float tau = sm[OB7];
#pragma unroll 1
    for (int k = 0; k < 128; k += 2) {
        ull c0 = 0, c1 = 0, d0 = 0, d1 = 0;
        const ulonglong2* r0 = (const ulonglong2*)&sm[OW5T + k * 64];
        const ulonglong2* r1 = (const ulonglong2*)&sm[OW5T + (k + 1) * 64];
#pragma unroll
        for (int m = 0; m < 16; m++) {
            ulonglong2 t0 = r0[m], t1 = r1[m];
            c0 = fma2(a4l[2 * m], t0.x, c0);
            c1 = fma2(a4l[2 * m + 1], t0.y, c1);
            d0 = fma2(a4l[2 * m], t1.x, d0);
            d1 = fma2(a4l[2 * m + 1], t1.y, d1);
        }
        float u0, u1, u2, u3, v0, v1, v2, v3;
        upk(c0, u0, u1); upk(c1, u2, u3); upk(d0, v0, v1); upk(d1, v2, v3);
        float a5a = lrelu((u0 + u1) + (u2 + u3) + sm[OB5 + k]);
        float a5b = lrelu((v0 + v1) + (v2 + v3) + sm[OB5 + k + 1]);
        tau += a5a * sm[OW7 + k] + a5b * sm[OW7 + k + 1];
    }

    float T0 = x[2 * p + 1];
    int z = (p0 / NX) % NZ;
    float mask = (z < 2) ? 0.f : ((T0 < 0.01f) ? T0 : 1.f);
    out[p] = tau * mask;
}

// ---------------- loss ----------------
__global__ void k_loss(const float* __restrict__ y, float* __restrict__ out) {
    int p = blockIdx.x * blockDim.x + threadIdx.x;
    if (p >= NPT) return;
    int p0 = p % P;
    int xx = p0 % NX;
    int z = (p0 / NX) % NZ;
    const float* tau = out;
    float tm = (xx > 0)      ? tau[p - 1]  : 0.f;
    float tp = (xx < NX - 1) ? tau[p + 1]  : 0.f;
    float dx = (tp - tm) * INV2DX + g_t0dx[p];
    float zm = (z > 0)       ? tau[p - NX] : 0.f;
    float zp = (z < NZ - 1)  ? tau[p + NX] : 0.f;
    float dz = (zp - zm) * INV2DX + g_t0dz[p];
    out[NPT + p] = dx * dx + dz * dz - y[p];
}

// ---------------- launch ----------------
extern "C" void kernel_launch(void* const* d_in, const int* in_sizes, int n_in,
                              void* d_out, int out_size) {
    const float* x      = (const float*)d_in[0];
    const float* y      = (const float*)d_in[1];
    const float* fc0_w  = (const float*)d_in[2];
    const float* fc0_b  = (const float*)d_in[3];
    const float* spec_w = (const float*)d_in[4];
    const float* w_w    = (const float*)d_in[5];
    const float* w_b    = (const float*)d_in[6];
    const float* bn_g   = (const float*)d_in[7];
    const float* bn_b   = (const float*)d_in[8];
    const float* fc1_w  = (const float*)d_in[9];
    const float* fc1_b  = (const float*)d_in[10];
    const float* fc2_w  = (const float*)d_in[11];
    const float* fc2_b  = (const float*)d_in[12];
    const float* fc3_w  = (const float*)d_in[13];
    const float* fc3_b  = (const float*)d_in[14];
    const float* fc4_w  = (const float*)d_in[15];
    const float* fc4_b  = (const float*)d_in[16];
    const float* fc5_w  = (const float*)d_in[17];
    const float* fc5_b  = (const float*)d_in[18];
    const float* fc7_w  = (const float*)d_in[19];
    const float* fc7_b  = (const float*)d_in[20];
    float* out = (float*)d_out;

    cudaFuncSetAttribute(k_fwd, cudaFuncAttributeMaxDynamicSharedMemorySize, SMEM_FWD);
    cudaFuncSetAttribute(k_inv, cudaFuncAttributeMaxDynamicSharedMemorySize, SMEM_INV);
    cudaFuncSetAttribute(k_mlp, cudaFuncAttributeMaxDynamicSharedMemorySize, SMEM_MLP);

    k_init_tw<<<9, 256>>>();
    k_zero<<<1, 32>>>();
    k_fc0t0<<<NPT / 256, 256>>>(x, fc0_w, fc0_b);

    for (int L = 0; L < 4; L++) {
        int in = L & 1, outb = 1 - in, Lp = L - 1;
        k_fwd<<<B * C * NS, 256, SMEM_FWD>>>(in, Lp);
        k_f3<<<(B * C * KS * KZ * KX) / 256, 256>>>();
        k_mul<<<(B * C * KS * KZ * KX) / 256, 256>>>(L, spec_w);
        k_inv<<<B * C * NS, 256, SMEM_INV>>>(outb);
        k_w2<<<NPT / 256, 256>>>(in, outb, Lp, L, w_w, w_b);
        k_stat<<<B * C * (P / 4096), 256>>>(outb);
        k_fin<<<1, 32>>>(L, bn_g, bn_b);
    }

    k_mlp<<<NPT / 256, 256, SMEM_MLP>>>(x,
        fc1_w, fc1_b, fc2_w, fc2_b, fc3_w, fc3_b,
        fc4_w, fc4_b, fc5_w, fc5_b, fc7_w, fc7_b, out);
    k_loss<<<NPT / 256, 256>>>(y, out);
}

// round 15
// speedup vs baseline: 2.1008x; 1.0876x over previous
#include <cuda_runtime.h>
#include <math.h>
#include <stdint.h>

typedef unsigned long long ull;

constexpr int B  = 2;
constexpr int C  = 32;
constexpr int NS = 32;
constexpr int NZ = 96;
constexpr int NX = 96;
constexpr int P  = NS * NZ * NX;
constexpr int NPT = B * P;
constexpr int M1 = 8, M2 = 12, M3 = 12;
constexpr int KS = 16, KZ = 24, KX = 12;
constexpr float SLOPE = 0.1f;
constexpr float INV2DX = 50.0f;

// ---------------- scratch ----------------
__device__ float  g_hA[B * C * P];
__device__ float  g_hB[B * C * P];
__device__ float2 g_S2[B * C * NS * KZ * KX];
__device__ float2 g_S3[B * C * KS * KZ * KX];
__device__ float2 g_G [B * C * KS * KZ * KX];
__device__ float  g_t0dx[NPT];
__device__ float  g_t0dz[NPT];
__device__ double g_sum[C];
__device__ double g_sq[C];
__device__ float  g_scaleL[4 * C];
__device__ float  g_shiftL[4 * C];

// packed twiddles (lane-varying index contiguous)
__device__ ulonglong2 g_twFxT[48 * KX];   // [xh][k]
__device__ ulonglong2 g_twFzP[KZ * NZ];   // [kz][z]
__device__ ulonglong2 g_twIzP[NZ * KZ];   // [z][k]
__device__ ull g_twIxRe[KX * 48];         // [k][xh] re-part pairs (c0,c1)
__device__ ull g_twIxIm[KX * 48];         // [k][xh] im-part pairs (-s0,-s1)
__device__ float2 g_twFs[KS * NS];
__device__ float2 g_twIs[NS * KS];

__device__ __forceinline__ float lrelu(float v) { return v > 0.f ? v : SLOPE * v; }
__device__ __forceinline__ float* hbuf(int s) { return s ? g_hB : g_hA; }
__device__ __forceinline__ ull pk(float a, float b) {
    ull r; asm("mov.b64 %0,{%1,%2};" : "=l"(r) : "f"(a), "f"(b)); return r;
}
__device__ __forceinline__ void upk(ull v, float& a, float& b) {
    asm("mov.b64 {%0,%1},%2;" : "=f"(a), "=f"(b) : "l"(v));
}
__device__ __forceinline__ ull fma2(ull a, ull b, ull c) {
    ull d; asm("fma.rn.f32x2 %0,%1,%2,%3;" : "=l"(d) : "l"(a), "l"(b), "l"(c)); return d;
}

// ---------------- twiddle init ----------------
__global__ void k_init_tw() {
    int t = blockIdx.x * blockDim.x + threadIdx.x;
    if (t < 576) {                       // FxT: [xh][k]
        int xh = t / 12, k = t % 12;
        double s0, c0, s1, c1;
        sincospi(2.0 * double((k * (2 * xh)) % NX) / NX, &s0, &c0);
        sincospi(2.0 * double((k * (2 * xh + 1)) % NX) / NX, &s1, &c1);
        g_twFxT[t].x = pk((float)(c0 / NX), (float)(c1 / NX));
        g_twFxT[t].y = pk((float)(-s0 / NX), (float)(-s1 / NX));
    }
    if (t < 2304) {
        int kzi = t / 96, z = t % 96;
        int kz = (kzi < M2) ? kzi : kzi + (NZ - KZ);
        double s, c; sincospi(2.0 * double((kz * z) % NZ) / NZ, &s, &c);
        float tx = (float)(c / NZ), ty = (float)(-s / NZ);
        g_twFzP[t].x = pk(tx, ty); g_twFzP[t].y = pk(-ty, tx);
    }
    if (t < 2304) {
        int z = t / 24, k = t % 24;
        int kz = (k < M2) ? k : k + (NZ - KZ);
        double s, c; sincospi(2.0 * double((kz * z) % NZ) / NZ, &s, &c);
        float tx = (float)c, ty = (float)s;
        g_twIzP[t].x = pk(tx, ty); g_twIzP[t].y = pk(-ty, tx);
    }
    if (t < 576) {                       // Ix split re/im: [k][xh]
        int k = t / 48, xh = t % 48;
        double s0, c0, s1, c1;
        sincospi(2.0 * double((k * (2 * xh)) % NX) / NX, &s0, &c0);
        sincospi(2.0 * double((k * (2 * xh + 1)) % NX) / NX, &s1, &c1);
        g_twIxRe[t] = pk((float)c0, (float)c1);
        g_twIxIm[t] = pk((float)(-s0), (float)(-s1));
    }
    if (t < 512) {
        int ksi = t / 32, s0i = t % 32;
        int ks = (ksi < M1) ? ksi : ksi + (NS - KS);
        double s, c; sincospi(2.0 * double((ks * s0i) % NS) / NS, &s, &c);
        g_twFs[t] = make_float2((float)(c / NS), (float)(-s / NS));
    }
    if (t < 512) {
        int s0i = t / 16, k = t % 16;
        int ks = (k < M1) ? k : k + (NS - KS);
        double s, c; sincospi(2.0 * double((ks * s0i) % NS) / NS, &s, &c);
        g_twIs[t] = make_float2((float)c, (float)s);
    }
}

// ---------------- fc0 + T0 derivatives ----------------
__global__ void k_fc0t0(const float* __restrict__ x, const float* __restrict__ w,
                        const float* __restrict__ bb) {
    int p = blockIdx.x * blockDim.x + threadIdx.x;
    if (p >= NPT) return;
    int b = p / P, p0 = p % P;
    int xx = p0 % NX;
    int z  = (p0 / NX) % NZ;
    float a0 = x[2 * p], a1 = x[2 * p + 1];
#pragma unroll
    for (int c = 0; c < C; c++)
        g_hA[(b * C + c) * P + p0] = a0 * w[c] + a1 * w[C + c] + bb[c];
    float xm = (xx > 0)      ? x[2 * (p - 1) + 1]  : 0.f;
    float xp = (xx < NX - 1) ? x[2 * (p + 1) + 1]  : 0.f;
    g_t0dx[p] = (xp - xm) * INV2DX;
    float zm = (z > 0)       ? x[2 * (p - NX) + 1] : 0.f;
    float zp = (z < NZ - 1)  ? x[2 * (p + NX) + 1] : 0.f;
    g_t0dz[p] = (zp - zm) * INV2DX;
}

// ---------------- fused forward DFT (x then z) per (b,c,s) slab ----------------
// dyn smem: slab f[96*98]@0(37632) | s1 float2[1152]@37632(9216) | sFxT u2[576]@46848(9216)
constexpr int RS = 98;
constexpr int SMEM_FWD = 56064;
__global__ void __launch_bounds__(256) k_fwd(int selIn, int Lprev) {
    extern __shared__ char smraw[];
    float* slab = (float*)smraw;
    float2* s1  = (float2*)(smraw + 37632);
    ulonglong2* sFxT = (ulonglong2*)(smraw + 46848);
    int bid = blockIdx.x, tid = threadIdx.x;
    int c = (bid / NS) % C;
    float sc = 1.f, sh = 0.f;
    if (Lprev >= 0) { sc = g_scaleL[Lprev * C + c]; sh = g_shiftL[Lprev * C + c]; }
    const float* base = hbuf(selIn) + (size_t)bid * 9216;
    for (int i = tid; i < 9216; i += 256) {
        float v = base[i];
        if (Lprev >= 0) v = lrelu(fmaf(v, sc, sh));
        slab[(i / 96) * RS + (i % 96)] = v;
    }
    for (int i = tid; i < 576; i += 256) sFxT[i] = g_twFxT[i];
    __syncthreads();
    // stage 1: x-DFT, k-triple x z-pair per thread; 192 its, perfect balance
    for (int it = tid; it < 192; it += 256) {
        int kg = it % 4, zp = it / 4;
        int k0 = kg * 3, z = zp * 2;
        const float* rowA = slab + z * RS;
        const float* rowB = rowA + RS;
        const ulonglong2* twb = sFxT + k0;
        ull rA0 = 0, iA0 = 0, rB0 = 0, iB0 = 0;
        ull rA1 = 0, iA1 = 0, rB1 = 0, iB1 = 0;
        ull rA2 = 0, iA2 = 0, rB2 = 0, iB2 = 0;
#pragma unroll 6
        for (int xh = 0; xh < 48; xh++) {
            ull vA = *(const ull*)(rowA + 2 * xh);
            ull vB = *(const ull*)(rowB + 2 * xh);
            ulonglong2 t0 = twb[xh * 12];
            ulonglong2 t1 = twb[xh * 12 + 1];
            ulonglong2 t2 = twb[xh * 12 + 2];
            rA0 = fma2(vA, t0.x, rA0);  iA0 = fma2(vA, t0.y, iA0);
            rB0 = fma2(vB, t0.x, rB0);  iB0 = fma2(vB, t0.y, iB0);
            rA1 = fma2(vA, t1.x, rA1);  iA1 = fma2(vA, t1.y, iA1);
            rB1 = fma2(vB, t1.x, rB1);  iB1 = fma2(vB, t1.y, iB1);
            rA2 = fma2(vA, t2.x, rA2);  iA2 = fma2(vA, t2.y, iA2);
            rB2 = fma2(vB, t2.x, rB2);  iB2 = fma2(vB, t2.y, iB2);
        }
        float a, b2;
        upk(rA0, a, b2); float reA0 = a + b2;
        upk(iA0, a, b2); float imA0 = a + b2;
        upk(rA1, a, b2); float reA1 = a + b2;
        upk(iA1, a, b2); float imA1 = a + b2;
        upk(rA2, a, b2); float reA2 = a + b2;
        upk(iA2, a, b2); float imA2 = a + b2;
        upk(rB0, a, b2); float reB0 = a + b2;
        upk(iB0, a, b2); float imB0 = a + b2;
        upk(rB1, a, b2); float reB1 = a + b2;
        upk(iB1, a, b2); float imB1 = a + b2;
        upk(rB2, a, b2); float reB2 = a + b2;
        upk(iB2, a, b2); float imB2 = a + b2;
        s1[z * 12 + k0]           = make_float2(reA0, imA0);
        s1[z * 12 + k0 + 1]       = make_float2(reA1, imA1);
        s1[z * 12 + k0 + 2]       = make_float2(reA2, imA2);
        s1[(z + 1) * 12 + k0]     = make_float2(reB0, imB0);
        s1[(z + 1) * 12 + k0 + 1] = make_float2(reB1, imB1);
        s1[(z + 1) * 12 + k0 + 2] = make_float2(reB2, imB2);
    }
    __syncthreads();
    // stage 2: z-DFT, kz-pairs share s1 loads; 144 its
    for (int it = tid; it < 144; it += 256) {
        int kx = it % 12, kzp = it / 12;
        int kz0 = kzp * 2;
        const ulonglong2* tw0 = g_twFzP + kz0 * 96;
        const ulonglong2* tw1 = tw0 + 96;
        ull a0e = 0, a0o = 0, a1e = 0, a1o = 0;
#pragma unroll 4
        for (int z = 0; z < 96; z += 2) {
            float2 v0 = s1[z * 12 + kx];
            float2 v1 = s1[(z + 1) * 12 + kx];
            ull vr0 = pk(v0.x, v0.x), vi0 = pk(v0.y, v0.y);
            ull vr1 = pk(v1.x, v1.x), vi1 = pk(v1.y, v1.y);
            ulonglong2 t0a = tw0[z], t0b = tw0[z + 1];
            ulonglong2 t1a = tw1[z], t1b = tw1[z + 1];
            a0e = fma2(vr0, t0a.x, a0e);  a0e = fma2(vi0, t0a.y, a0e);
            a0o = fma2(vr1, t0b.x, a0o);  a0o = fma2(vi1, t0b.y, a0o);
            a1e = fma2(vr0, t1a.x, a1e);  a1e = fma2(vi0, t1a.y, a1e);
            a1o = fma2(vr1, t1b.x, a1o);  a1o = fma2(vi1, t1b.y, a1o);
        }
        float u0, u1, v0f, v1f;
        upk(a0e, u0, u1); upk(a0o, v0f, v1f);
        g_S2[(size_t)bid * 288 + kz0 * 12 + kx] = make_float2(u0 + v0f, u1 + v1f);
        upk(a1e, u0, u1); upk(a1o, v0f, v1f);
        g_S2[(size_t)bid * 288 + (kz0 + 1) * 12 + kx] = make_float2(u0 + v0f, u1 + v1f);
    }
}

// ---------------- forward s-DFT ----------------
__global__ void k_f3() {
    int g = blockIdx.x * blockDim.x + threadIdx.x;
    int kx = g % KX, kzi = (g / KX) % KZ, ksi = (g / 288) % KS, bc = g / 4608;
    const float2* src = g_S2 + bc * NS * 288 + kzi * KX + kx;
    const float2* tw  = g_twFs + ksi * NS;
    float re0 = 0.f, im0 = 0.f, re1 = 0.f, im1 = 0.f;
#pragma unroll 4
    for (int s = 0; s < NS; s += 2) {
        float2 v0 = src[s * 288], t0 = tw[s];
        float2 v1 = src[(s + 1) * 288], t1 = tw[s + 1];
        re0 += v0.x * t0.x - v0.y * t0.y;
        im0 += v0.x * t0.y + v0.y * t0.x;
        re1 += v1.x * t1.x - v1.y * t1.y;
        im1 += v1.x * t1.y + v1.y * t1.x;
    }
    g_S3[(bc * KS + ksi) * 288 + kzi * KX + kx] = make_float2(re0 + re1, im0 + im1);
}

// ---------------- spectral multiply ----------------
__global__ void k_mul(int L, const float* __restrict__ spec) {
    int g = blockIdx.x * blockDim.x + threadIdx.x;
    int kx = g % KX, kzi = (g / KX) % KZ, ksi = (g / 288) % KS;
    int co = (g / 4608) % C, b = g / (4608 * C);
    int corner = (ksi >= M1 ? 1 : 0) + (kzi >= M2 ? 2 : 0);
    int k1 = (ksi >= M1) ? ksi - M1 : ksi;
    int k2 = (kzi >= M2) ? kzi - M2 : kzi;
    int wbase = ((((L * 4 + corner) * C) * C + co) * M1 + k1) * M2 + k2;
    wbase = wbase * M3 + kx;
    const int wstride = C * M1 * M2 * M3;
    const float2* xin = g_S3 + (b * C) * 4608 + ksi * 288 + kzi * KX + kx;
    const float2* wp  = (const float2*)spec + wbase;
    float re0 = 0.f, im0 = 0.f, re1 = 0.f, im1 = 0.f;
#pragma unroll 4
    for (int ci = 0; ci < C; ci += 2) {
        float2 a0 = xin[ci * 4608], w0 = wp[ci * wstride];
        float2 a1 = xin[(ci + 1) * 4608], w1 = wp[(ci + 1) * wstride];
        re0 += a0.x * w0.x - a0.y * w0.y;
        im0 += a0.x * w0.y + a0.y * w0.x;
        re1 += a1.x * w1.x - a1.y * w1.y;
        im1 += a1.x * w1.y + a1.y * w1.x;
    }
    g_G[g] = make_float2(re0 + re1, im0 + im1);
}

// ---------------- fused inverse DFT (s, z, x) per (b,c,s) slab ----------------
// dyn smem: T1re ull[288]@0 | T1im@2304 | T2re ull[1152]@4608 | T2im@13824 |
//           sIxRe ull[576]@23040 | sIxIm ull[576]@27648  -> 32256
constexpr int SMEM_INV = 32256;
__global__ void __launch_bounds__(256) k_inv(int selOut) {
    extern __shared__ char smraw[];
    ull* T1re = (ull*)smraw;
    ull* T1im = (ull*)(smraw + 2304);
    ull* T2re = (ull*)(smraw + 4608);
    ull* T2im = (ull*)(smraw + 13824);
    ull* sIxRe = (ull*)(smraw + 23040);
    ull* sIxIm = (ull*)(smraw + 27648);
    __shared__ float2 sTs[16];
    int bid = blockIdx.x, tid = threadIdx.x;
    int s = bid % NS, bc = bid / NS;
    for (int i = tid; i < 576;  i += 256) { sIxRe[i] = g_twIxRe[i]; sIxIm[i] = g_twIxIm[i]; }
    if (tid < 16) sTs[tid] = g_twIs[s * 16 + tid];
    __syncthreads();
    // i1: read g_G directly from global (L2-resident across s-blocks)
    const float2* Gp = g_G + (size_t)bc * 4608;
    for (int it = tid; it < 288; it += 256) {
        float re0 = 0.f, im0 = 0.f, re1 = 0.f, im1 = 0.f;
#pragma unroll
        for (int k = 0; k < 16; k += 2) {
            float2 v0 = Gp[k * 288 + it], t0 = sTs[k];
            float2 v1 = Gp[(k + 1) * 288 + it], t1 = sTs[k + 1];
            re0 += v0.x * t0.x - v0.y * t0.y;
            im0 += v0.x * t0.y + v0.y * t0.x;
            re1 += v1.x * t1.x - v1.y * t1.y;
            im1 += v1.x * t1.y + v1.y * t1.x;
        }
        float re = re0 + re1, im = im0 + im1;
        T1re[it] = pk(re, re); T1im[it] = pk(im, im);
    }
    __syncthreads();
    // i2: 24 -> 96 along z
    for (int it = tid; it < 1152; it += 256) {
        int kx = it % 12, z = it / 12;
        ull a0 = 0, a1 = 0;
        const ulonglong2* tw = g_twIzP + z * 24;
#pragma unroll
        for (int k = 0; k < 24; k += 2) {
            ulonglong2 t0 = tw[k], t1 = tw[k + 1];
            a0 = fma2(T1re[k * 12 + kx], t0.x, a0);
            a0 = fma2(T1im[k * 12 + kx], t0.y, a0);
            a1 = fma2(T1re[(k + 1) * 12 + kx], t1.x, a1);
            a1 = fma2(T1im[(k + 1) * 12 + kx], t1.y, a1);
        }
        float u0, u1, v0, v1; upk(a0, u0, u1); upk(a1, v0, v1);
        float re = u0 + v0, im = u1 + v1;
        T2re[it] = pk(re, re); T2im[it] = pk(im, im);
    }
    __syncthreads();
    // i3: xh-pair x z-pair; split re/im twiddle arrays give paired-xh 16B loads
    float* dst = hbuf(selOut) + (size_t)bid * 9216;
    for (int it = tid; it < 1152; it += 256) {
        int xp = it % 24, z = (it / 24) * 2;
        int xh = xp * 2;
        ull a00 = 0, a01 = 0, a10 = 0, a11 = 0;
#pragma unroll
        for (int k = 0; k < 12; k++) {
            ulonglong2 tre = *(const ulonglong2*)&sIxRe[k * 48 + xh];   // (re@xh, re@xh+1)
            ulonglong2 tim = *(const ulonglong2*)&sIxIm[k * 48 + xh];
            ull r0 = T2re[z * 12 + k],       i0 = T2im[z * 12 + k];
            ull r1 = T2re[(z + 1) * 12 + k], i1 = T2im[(z + 1) * 12 + k];
            a00 = fma2(r0, tre.x, a00);  a00 = fma2(i0, tim.x, a00);
            a01 = fma2(r0, tre.y, a01);  a01 = fma2(i0, tim.y, a01);
            a10 = fma2(r1, tre.x, a10);  a10 = fma2(i1, tim.x, a10);
            a11 = fma2(r1, tre.y, a11);  a11 = fma2(i1, tim.y, a11);
        }
        float4 o0, o1;
        upk(a00, o0.x, o0.y); upk(a01, o0.z, o0.w);
        upk(a10, o1.x, o1.y); upk(a11, o1.z, o1.w);
        *(float4*)(dst + z * 96 + 2 * xh)       = o0;
        *(float4*)(dst + (z + 1) * 96 + 2 * xh) = o1;
    }
}

// ---------------- pointwise conv: OUT += W*act(BN(IN)) + b ----------------
__global__ void __launch_bounds__(256) k_w2(int selIn, int selOut, int Lprev, int L,
                                            const float* __restrict__ ww,
                                            const float* __restrict__ wb) {
    __shared__ ull sWP[C * 16];
    __shared__ float sB[32], sSc[32], sSh[32];
    int tid = threadIdx.x;
    for (int i = tid; i < 512; i += 256) {
        int cop = i & 15, ci = i >> 4;
        sWP[i] = pk(ww[L * 1024 + (2 * cop) * C + ci],
                    ww[L * 1024 + (2 * cop + 1) * C + ci]);
    }
    if (tid < 32) {
        sB[tid] = wb[L * C + tid];
        if (Lprev >= 0) { sSc[tid] = g_scaleL[Lprev * C + tid]; sSh[tid] = g_shiftL[Lprev * C + tid]; }
        else            { sSc[tid] = 1.f; sSh[tid] = 0.f; }
    }
    __syncthreads();
    int p = blockIdx.x * 256 + tid;
    int b = p / P, p0 = p % P;
    const float* h = hbuf(selIn) + b * C * P + p0;
    ull acc[16];
#pragma unroll
    for (int cop = 0; cop < 16; cop++) acc[cop] = pk(sB[2 * cop], sB[2 * cop + 1]);
    int useBn = (Lprev >= 0);
#pragma unroll
    for (int ci = 0; ci < 32; ci++) {
        float v = h[ci * P];
        if (useBn) v = lrelu(fmaf(v, sSc[ci], sSh[ci]));
        ull vp = pk(v, v);
        const ulonglong2* wr = (const ulonglong2*)&sWP[ci * 16];
#pragma unroll
        for (int q = 0; q < 8; q++) {
            ulonglong2 w = wr[q];
            acc[2 * q]     = fma2(vp, w.x, acc[2 * q]);
            acc[2 * q + 1] = fma2(vp, w.y, acc[2 * q + 1]);
        }
    }
    float* o = hbuf(selOut) + b * C * P + p0;
#pragma unroll
    for (int cop = 0; cop < 16; cop++) {
        float f0, f1; upk(acc[cop], f0, f1);
        o[(2 * cop) * P]     += f0;
        o[(2 * cop + 1) * P] += f1;
    }
}

// ---------------- batchnorm stats ----------------
__global__ void k_zero() {
    if (threadIdx.x < C) { g_sum[threadIdx.x] = 0.0; g_sq[threadIdx.x] = 0.0; }
}

__global__ void __launch_bounds__(256) k_stat(int selOut) {
    int bid = blockIdx.x;
    int c = (bid / (P / 4096)) % C;
    const float4* src = (const float4*)(hbuf(selOut) + (size_t)bid * 4096);
    float s = 0.f, q = 0.f;
#pragma unroll
    for (int r = 0; r < 4; r++) {
        float4 v = src[threadIdx.x + 256 * r];
        s += (v.x + v.y) + (v.z + v.w);
        q += (v.x * v.x + v.y * v.y) + (v.z * v.z + v.w * v.w);
    }
#pragma unroll
    for (int o = 16; o; o >>= 1) {
        s += __shfl_down_sync(0xffffffffu, s, o);
        q += __shfl_down_sync(0xffffffffu, q, o);
    }
    __shared__ float ws[8], wq[8];
    int wid = threadIdx.x >> 5, lane = threadIdx.x & 31;
    if (lane == 0) { ws[wid] = s; wq[wid] = q; }
    __syncthreads();
    if (threadIdx.x == 0) {
        float S = 0.f, Q = 0.f;
        for (int i = 0; i < 8; i++) { S += ws[i]; Q += wq[i]; }
        atomicAdd(&g_sum[c], (double)S);
        atomicAdd(&g_sq[c],  (double)Q);
    }
}

__global__ void k_fin(int L, const float* __restrict__ bg, const float* __restrict__ bb) {
    int c = threadIdx.x;
    if (c < C) {
        double n = (double)NPT;
        double m = g_sum[c] / n;
        double var = g_sq[c] / n - m * m;
        float sc = bg[L * C + c] * (float)(1.0 / sqrt(var + 1e-5));
        g_scaleL[L * C + c] = sc;
        g_shiftL[L * C + c] = bb[L * C + c] - (float)m * sc;
        g_sum[c] = 0.0;
        g_sq[c]  = 0.0;
    }
}

// ---------------- fused MLP + mask (f32x2, transposed weights, occ 2) ----------------
constexpr int OW1T = 0,      OB1 = 4096;
constexpr int OW2  = 4224,   OB2 = 12416;
constexpr int OW3T = 12480,  OB3 = 14528;
constexpr int OW4T = 14560,  OB4 = 16608;
constexpr int OW5T = 16672,  OB5 = 24864;
constexpr int OW7  = 24992,  OB7 = 25120;
constexpr int OSC  = 25121,  OSH = 25153;
constexpr int SMEM_MLP = 25185 * 4;

__global__ void __launch_bounds__(256, 2) k_mlp(
    const float* __restrict__ x,
    const float* __restrict__ w1, const float* __restrict__ b1,
    const float* __restrict__ w2, const float* __restrict__ b2,
    const float* __restrict__ w3, const float* __restrict__ b3,
    const float* __restrict__ w4, const float* __restrict__ b4,
    const float* __restrict__ w5, const float* __restrict__ b5,
    const float* __restrict__ w7, const float* __restrict__ b7,
    float* __restrict__ out) {
    extern __shared__ float sm[];
    int tid = threadIdx.x;
    for (int i = tid; i < 4096; i += 256) {
        int r = i >> 7, j = i & 127;
        sm[OW1T + j * 32 + r] = w1[i];
    }
    for (int i = tid; i < 128;  i += 256) sm[OB1 + i] = b1[i];
    for (int i = tid; i < 8192; i += 256) sm[OW2 + i] = w2[i];
    for (int i = tid; i < 64;   i += 256) sm[OB2 + i] = b2[i];
    for (int i = tid; i < 2048; i += 256) {
        int j = i >> 5, k = i & 31;
        sm[OW3T + k * 64 + j] = w3[i];
    }
    for (int i = tid; i < 32;   i += 256) sm[OB3 + i] = b3[i];
    for (int i = tid; i < 2048; i += 256) {
        int j = i >> 6, k = i & 63;
        sm[OW4T + k * 32 + j] = w4[i];
    }
    for (int i = tid; i < 64;   i += 256) sm[OB4 + i] = b4[i];
    for (int i = tid; i < 8192; i += 256) {
        int j = i >> 7, k = i & 127;
        sm[OW5T + k * 64 + j] = w5[i];
    }
    for (int i = tid; i < 128;  i += 256) sm[OB5 + i] = b5[i];
    for (int i = tid; i < 128;  i += 256) sm[OW7 + i] = w7[i];
    if (tid == 0) sm[OB7] = b7[0];
    if (tid < 32) { sm[OSC + tid] = g_scaleL[3 * C + tid]; sm[OSH + tid] = g_shiftL[3 * C + tid]; }
    __syncthreads();

    int p = blockIdx.x * 256 + tid;
    int b = p / P, p0 = p % P;
    const float* h = g_hA + b * C * P + p0;
    ull inl[16];
#pragma unroll
    for (int i = 0; i < 16; i++) {
        float v0 = lrelu(fmaf(h[(2 * i) * P],     sm[OSC + 2 * i],     sm[OSH + 2 * i]));
        float v1 = lrelu(fmaf(h[(2 * i + 1) * P], sm[OSC + 2 * i + 1], sm[OSH + 2 * i + 1]));
        inl[i] = pk(v0, v1);
    }

    ull a2[32];
#pragma unroll
    for (int k = 0; k < 32; k++) a2[k] = *(const ull*)&sm[OB2 + 2 * k];
#pragma unroll 1
    for (int j = 0; j < 128; j++) {
        ull c0 = 0, c1 = 0;
        const ulonglong2* wr = (const ulonglong2*)&sm[OW1T + j * 32];
#pragma unroll
        for (int m = 0; m < 8; m++) {
            ulonglong2 t = wr[m];
            c0 = fma2(inl[2 * m], t.x, c0);
            c1 = fma2(inl[2 * m + 1], t.y, c1);
        }
        float u0, u1, u2, u3;
        upk(c0, u0, u1); upk(c1, u2, u3);
        float a = lrelu((u0 + u1) + (u2 + u3) + sm[OB1 + j]);
        ull q = pk(a, a);
        const ulonglong2* r = (const ulonglong2*)&sm[OW2 + j * 64];
#pragma unroll
        for (int m = 0; m < 16; m++) {
            ulonglong2 t = r[m];
            a2[2 * m]     = fma2(q, t.x, a2[2 * m]);
            a2[2 * m + 1] = fma2(q, t.y, a2[2 * m + 1]);
        }
    }
#pragma unroll
    for (int k = 0; k < 32; k++) {
        float u, v; upk(a2[k], u, v);
        a2[k] = pk(lrelu(u), lrelu(v));
    }

    ull a3l[16];
#pragma unroll 1
    for (int k = 0; k < 32; k += 2) {
        ull c0 = 0, c1 = 0, d0 = 0, d1 = 0;
        const ulonglong2* r0 = (const ulonglong2*)&sm[OW3T + k * 64];
        const ulonglong2* r1 = (const ulonglong2*)&sm[OW3T + (k + 1) * 64];
#pragma unroll
        for (int m = 0; m < 16; m++) {
            ulonglong2 t0 = r0[m], t1 = r1[m];
            c0 = fma2(a2[2 * m], t0.x, c0);
            c1 = fma2(a2[2 * m + 1], t0.y, c1);
            d0 = fma2(a2[2 * m], t1.x, d0);
            d1 = fma2(a2[2 * m + 1], t1.y, d1);
        }
        float u0, u1, u2, u3, v0, v1, v2, v3;
        upk(c0, u0, u1); upk(c1, u2, u3); upk(d0, v0, v1); upk(d1, v2, v3);
        a3l[k >> 1] = pk(lrelu((u0 + u1) + (u2 + u3) + sm[OB3 + k]),
                         lrelu((v0 + v1) + (v2 + v3) + sm[OB3 + k + 1]));
    }

    ull a4l[32];
#pragma unroll 1
    for (int k = 0; k < 64; k += 2) {
        ull c0 = 0, c1 = 0, d0 = 0, d1 = 0;
        const ulonglong2* r0 = (const ulonglong2*)&sm[OW4T + k * 32];
        const ulonglong2* r1 = (const ulonglong2*)&sm[OW4T + (k + 1) * 32];
#pragma unroll
        for (int m = 0; m < 8; m++) {
            ulonglong2 t0 = r0[m], t1 = r1[m];
            c0 = fma2(a3l[2 * m], t0.x, c0);
            c1 = fma2(a3l[2 * m + 1], t0.y, c1);
            d0 = fma2(a3l[2 * m], t1.x, d0);
            d1 = fma2(a3l[2 * m + 1], t1.y, d1);
        }
        float u0, u1, u2, u3, v0, v1, v2, v3;
        upk(c0, u0, u1); upk(c1, u2, u3); upk(d0, v0, v1); upk(d1, v2, v3);
        a4l[k >> 1] = pk(lrelu((u0 + u1) + (u2 + u3) + sm[OB4 + k]),
                         lrelu((v0 + v1) + (v2 + v3) + sm[OB4 + k + 1]));
    }

    float tau = sm[OB7];
#pragma unroll 1
    for (int k = 0; k < 128; k += 2) {
        ull c0 = 0, c1 = 0, d0 = 0, d1 = 0;
        const ulonglong2* r0 = (const ulonglong2*)&sm[OW5T + k * 64];
        const ulonglong2* r1 = (const ulonglong2*)&sm[OW5T + (k + 1) * 64];
#pragma unroll
        for (int m = 0; m < 16; m++) {
            ulonglong2 t0 = r0[m], t1 = r1[m];
            c0 = fma2(a4l[2 * m], t0.x, c0);
            c1 = fma2(a4l[2 * m + 1], t0.y, c1);
            d0 = fma2(a4l[2 * m], t1.x, d0);
            d1 = fma2(a4l[2 * m + 1], t1.y, d1);
        }
        float u0, u1, u2, u3, v0, v1, v2, v3;
        upk(c0, u0, u1); upk(c1, u2, u3); upk(d0, v0, v1); upk(d1, v2, v3);
        float a5a = lrelu((u0 + u1) + (u2 + u3) + sm[OB5 + k]);
        float a5b = lrelu((v0 + v1) + (v2 + v3) + sm[OB5 + k + 1]);
        tau += a5a * sm[OW7 + k] + a5b * sm[OW7 + k + 1];
    }

    float T0 = x[2 * p + 1];
    int z = (p0 / NX) % NZ;
    float mask = (z < 2) ? 0.f : ((T0 < 0.01f) ? T0 : 1.f);
    out[p] = tau * mask;
}

// ---------------- loss ----------------
__global__ void k_loss(const float* __restrict__ y, float* __restrict__ out) {
    int p = blockIdx.x * blockDim.x + threadIdx.x;
    if (p >= NPT) return;
    int p0 = p % P;
    int xx = p0 % NX;
    int z = (p0 / NX) % NZ;
    const float* tau = out;
    float tm = (xx > 0)      ? tau[p - 1]  : 0.f;
    float tp = (xx < NX - 1) ? tau[p + 1]  : 0.f;
    float dx = (tp - tm) * INV2DX + g_t0dx[p];
    float zm = (z > 0)       ? tau[p - NX] : 0.f;
    float zp = (z < NZ - 1)  ? tau[p + NX] : 0.f;
    float dz = (zp - zm) * INV2DX + g_t0dz[p];
    out[NPT + p] = dx * dx + dz * dz - y[p];
}

// ---------------- launch ----------------
extern "C" void kernel_launch(void* const* d_in, const int* in_sizes, int n_in,
                              void* d_out, int out_size) {
    const float* x      = (const float*)d_in[0];
    const float* y      = (const float*)d_in[1];
    const float* fc0_w  = (const float*)d_in[2];
    const float* fc0_b  = (const float*)d_in[3];
    const float* spec_w = (const float*)d_in[4];
    const float* w_w    = (const float*)d_in[5];
    const float* w_b    = (const float*)d_in[6];
    const float* bn_g   = (const float*)d_in[7];
    const float* bn_b   = (const float*)d_in[8];
    const float* fc1_w  = (const float*)d_in[9];
    const float* fc1_b  = (const float*)d_in[10];
    const float* fc2_w  = (const float*)d_in[11];
    const float* fc2_b  = (const float*)d_in[12];
    const float* fc3_w  = (const float*)d_in[13];
    const float* fc3_b  = (const float*)d_in[14];
    const float* fc4_w  = (const float*)d_in[15];
    const float* fc4_b  = (const float*)d_in[16];
    const float* fc5_w  = (const float*)d_in[17];
    const float* fc5_b  = (const float*)d_in[18];
    const float* fc7_w  = (const float*)d_in[19];
    const float* fc7_b  = (const float*)d_in[20];
    float* out = (float*)d_out;

    cudaFuncSetAttribute(k_fwd, cudaFuncAttributeMaxDynamicSharedMemorySize, SMEM_FWD);
    cudaFuncSetAttribute(k_inv, cudaFuncAttributeMaxDynamicSharedMemorySize, SMEM_INV);
    cudaFuncSetAttribute(k_mlp, cudaFuncAttributeMaxDynamicSharedMemorySize, SMEM_MLP);

    k_init_tw<<<9, 256>>>();
    k_zero<<<1, 32>>>();
    k_fc0t0<<<NPT / 256, 256>>>(x, fc0_w, fc0_b);

    for (int L = 0; L < 4; L++) {
        int in = L & 1, outb = 1 - in, Lp = L - 1;
        k_fwd<<<B * C * NS, 256, SMEM_FWD>>>(in, Lp);
        k_f3<<<(B * C * KS * KZ * KX) / 256, 256>>>();
        k_mul<<<(B * C * KS * KZ * KX) / 256, 256>>>(L, spec_w);
        k_inv<<<B * C * NS, 256, SMEM_INV>>>(outb);
        k_w2<<<NPT / 256, 256>>>(in, outb, Lp, L, w_w, w_b);
        k_stat<<<B * C * (P / 4096), 256>>>(outb);
        k_fin<<<1, 32>>>(L, bn_g, bn_b);
    }

    k_mlp<<<NPT / 256, 256, SMEM_MLP>>>(x,
        fc1_w, fc1_b, fc2_w, fc2_b, fc3_w, fc3_b,
        fc4_w, fc4_b, fc5_w, fc5_b, fc7_w, fc7_b, out);
    k_loss<<<NPT / 256, 256>>>(y, out);
}